// round 12
// baseline (speedup 1.0000x reference)
#include <cuda_runtime.h>
#include <cuda_fp16.h>
#include <cuda_fp8.h>
#include <math.h>
#include <stdint.h>

#define N_NODES  100000
#define N_EDGES  1600000
#define N_GRAPHS 2048
#define H        256

#define SCAN_NBLK ((N_NODES + 1023) / 1024)   // 98 blocks of 1024

// ---------------- scratch (device globals; no allocs allowed) ----------------
__device__ int   g_ideg[N_NODES];
__device__ int   g_off[N_NODES];
__device__ int   g_cursor[N_NODES];
__device__ int   g_csr[N_EDGES];
__device__ int   g_bsum[SCAN_NBLK];
__device__ int   g_bscan[SCAN_NBLK];
__device__ float g_dinv[N_NODES];
__device__ float g_gsum[N_GRAPHS * H];
__device__ float g_gcnt[N_GRAPHS];
// node features
__device__ __half g_xs[(size_t)N_NODES * 128];            // dinv * x (fp16, gather L1)
__device__ __half g_z1[(size_t)N_NODES * 128];            // gemm1 A (fp16)
__device__ unsigned char g_h1s[(size_t)N_NODES * H];      // dinv*relu(...) fp8 e4m3 (gather L2)
__device__ __half g_z2[(size_t)N_NODES * H];              // gemm2 A (fp16)
__device__ __half g_w1[256 * 128];
__device__ __half g_w2[256 * 256];

// ================= warp-MMA helpers (sm_80-class, compile for compute_103) ==
__device__ __forceinline__ uint32_t smem_u32(const void* p) {
    uint32_t a;
    asm("{ .reg .u64 t; cvta.to.shared.u64 t, %1; cvt.u32.u64 %0, t; }" : "=r"(a) : "l"(p));
    return a;
}
__device__ __forceinline__ void ldm_x4(uint32_t* r, uint32_t addr) {
    asm volatile("ldmatrix.sync.aligned.m8n8.x4.shared.b16 {%0,%1,%2,%3}, [%4];"
                 : "=r"(r[0]), "=r"(r[1]), "=r"(r[2]), "=r"(r[3]) : "r"(addr));
}
__device__ __forceinline__ void mma16816(float* d, const uint32_t* a, const uint32_t* b) {
    asm volatile("mma.sync.aligned.m16n8k16.row.col.f32.f16.f16.f32 "
                 "{%0,%1,%2,%3}, {%4,%5,%6,%7}, {%8,%9}, {%0,%1,%2,%3};"
                 : "+f"(d[0]), "+f"(d[1]), "+f"(d[2]), "+f"(d[3])
                 : "r"(a[0]), "r"(a[1]), "r"(a[2]), "r"(a[3]), "r"(b[0]), "r"(b[1]));
}
__device__ __forceinline__ void cp16(uint32_t dst, const void* src) {
    asm volatile("cp.async.ca.shared.global [%0], [%1], 16;" :: "r"(dst), "l"(src));
}
#define CP_COMMIT() asm volatile("cp.async.commit_group;" ::: "memory")
#define CP_WAIT1()  asm volatile("cp.async.wait_group 1;" ::: "memory")
#define CP_WAIT0()  asm volatile("cp.async.wait_group 0;" ::: "memory")

// accumulate 16 fp8(e4m3) values (one uint4) into acc[16]
__device__ __forceinline__ void fp8x16_acc(uint4 u, float* acc) {
    const __nv_fp8x2_storage_t* p = (const __nv_fp8x2_storage_t*)&u;  // 8 pairs
#pragma unroll
    for (int q = 0; q < 8; ++q) {
        __half2_raw hr = __nv_cvt_fp8x2_to_halfraw2(p[q], __NV_E4M3);
        float2 f = __half22float2(*(__half2*)&hr);
        acc[2 * q]     += f.x;
        acc[2 * q + 1] += f.y;
    }
}

// ---------------- prep kernels ----------------

__global__ void zero_kernel() {
    int i = blockIdx.x * blockDim.x + threadIdx.x;     // grid covers N_GRAPHS*H = 524288
    if (i < N_NODES) { g_ideg[i] = 0; g_cursor[i] = 0; }
    if (i < N_GRAPHS * H) g_gsum[i] = 0.f;
    if (i < N_GRAPHS)     g_gcnt[i] = 0.f;
}

__global__ void deg_kernel(const int* __restrict__ dst) {
    int e = blockIdx.x * blockDim.x + threadIdx.x;
    if (e < N_EDGES) atomicAdd(&g_ideg[dst[e]], 1);
}

__global__ void scan1_kernel() {
    __shared__ int sh[256];
    int tid = threadIdx.x;
    int base = blockIdx.x * 1024 + tid * 4;
    int v[4]; int s = 0;
#pragma unroll
    for (int k = 0; k < 4; ++k) {
        int i = base + k;
        v[k] = (i < N_NODES) ? g_ideg[i] : 0;
        s += v[k];
    }
    sh[tid] = s; __syncthreads();
#pragma unroll
    for (int o = 1; o < 256; o <<= 1) {
        int t = (tid >= o) ? sh[tid - o] : 0;
        __syncthreads(); sh[tid] += t; __syncthreads();
    }
    int run = sh[tid] - s;
#pragma unroll
    for (int k = 0; k < 4; ++k) {
        int i = base + k;
        if (i < N_NODES) g_off[i] = run;
        run += v[k];
    }
    if (tid == 255) g_bsum[blockIdx.x] = sh[255];
}

__global__ void scan2_kernel() {
    __shared__ int sh[128];
    int tid = threadIdx.x;
    int v = (tid < SCAN_NBLK) ? g_bsum[tid] : 0;
    sh[tid] = v; __syncthreads();
#pragma unroll
    for (int o = 1; o < 128; o <<= 1) {
        int t = (tid >= o) ? sh[tid - o] : 0;
        __syncthreads(); sh[tid] += t; __syncthreads();
    }
    if (tid < SCAN_NBLK) g_bscan[tid] = sh[tid] - v;
}

__global__ void scan3_kernel() {
    int i = blockIdx.x * blockDim.x + threadIdx.x;
    if (i < N_NODES) g_off[i] += g_bscan[i >> 10];
}

__global__ void fill_kernel(const int* __restrict__ src, const int* __restrict__ dst) {
    int e = blockIdx.x * blockDim.x + threadIdx.x;
    if (e < N_EDGES) {
        int d = dst[e];
        int pos = g_off[d] + atomicAdd(&g_cursor[d], 1);
        g_csr[pos] = src[e];
    }
}

__global__ void prep_kernel(const int* __restrict__ batch) {
    int i = blockIdx.x * blockDim.x + threadIdx.x;
    if (i < N_NODES) {
        g_dinv[i] = rsqrtf((float)g_ideg[i] + 1.0f);
        atomicAdd(&g_gcnt[batch[i]], 1.0f);
    }
}

// xs = dinv[node] * x (fp16); one float4 per thread. Runs AFTER prep.
__global__ void convert_x_kernel(const float* __restrict__ x) {
    int i = blockIdx.x * blockDim.x + threadIdx.x;     // N_NODES*128/4 threads exactly
    float dv = g_dinv[i >> 5];
    float4 v = ((const float4*)x)[i];
    ((__half2*)g_xs)[i * 2 + 0] = __floats2half2_rn(v.x * dv, v.y * dv);
    ((__half2*)g_xs)[i * 2 + 1] = __floats2half2_rn(v.z * dv, v.w * dv);
}

// transpose W[K,256] -> Wt [256,K] fp16
__global__ void split_w_kernel(const float* __restrict__ W,
                               __half* __restrict__ T, int K) {
    int i = blockIdx.x * blockDim.x + threadIdx.x;     // K*256 threads
    if (i < K * 256) {
        int k = i >> 8;
        int n = i & 255;
        T[n * K + k] = __float2half_rn(W[i]);          // coalesced read
    }
}

// ---------------- layer-1 aggregation on xs (128 fp16 cols, 256 B rows) -----
// One warp per node; half-warps process alternating edges, 16 lanes x uint4.
__global__ void __launch_bounds__(256)
agg1_kernel()
{
    int warp = threadIdx.x >> 5;
    int lane = threadIdx.x & 31;
    int node = blockIdx.x * 8 + warp;          // grid.x = 12500, exact
    int half = lane >> 4;
    int coff = (lane & 15) * 8;                // 16 lanes x 8 halfs = 128 cols
    size_t rbase = (size_t)node * 128 + coff;

    float acc[8];
#pragma unroll
    for (int q = 0; q < 8; ++q) acc[q] = 0.f;

    if (half == 0) {                            // self-loop term: xs[d]
        uint4 u = *(const uint4*)(g_xs + rbase);
        const __half2* hp = (const __half2*)&u;
#pragma unroll
        for (int q = 0; q < 4; ++q) {
            float2 f = __half22float2(hp[q]);
            acc[q * 2] += f.x; acc[q * 2 + 1] += f.y;
        }
    }

    int beg = g_off[node];
    int cnt = g_ideg[node];
    const int* nb = g_csr + beg;
    for (int j = half; j < cnt; j += 2) {
        int s = nb[j];
        uint4 u = *(const uint4*)(g_xs + (size_t)s * 128 + coff);
        const __half2* hp = (const __half2*)&u;
#pragma unroll
        for (int q = 0; q < 4; ++q) {
            float2 f = __half22float2(hp[q]);
            acc[q * 2] += f.x; acc[q * 2 + 1] += f.y;
        }
    }

    // combine half-warps (lane i <-> i^16 share coff)
#pragma unroll
    for (int q = 0; q < 8; ++q)
        acc[q] += __shfl_xor_sync(0xffffffffu, acc[q], 16);

    if (half == 0) {
        float dv = g_dinv[node];
        __half2 h[4];
#pragma unroll
        for (int q = 0; q < 4; ++q)
            h[q] = __floats2half2_rn(acc[q * 2] * dv, acc[q * 2 + 1] * dv);
        *(uint4*)(g_z1 + rbase) = *(uint4*)h;
    }
}

// ---------------- layer-2 aggregation on h1s (256 fp8 cols, 256 B rows) -----
// Same half-warp scheme: 16 lanes x uint4 = 16 fp8 cols/lane = full row;
// two edges in flight per warp. z2 = dinv[d] * (sum + self), fp16 out.
__global__ void __launch_bounds__(256)
agg2_kernel()
{
    int warp = threadIdx.x >> 5;
    int lane = threadIdx.x & 31;
    int node = blockIdx.x * 8 + warp;          // grid.x = 12500
    int half = lane >> 4;
    int coff = (lane & 15) * 16;               // 16 lanes x 16 fp8 = 256 cols
    size_t rbase = (size_t)node * H + coff;

    float acc[16];
#pragma unroll
    for (int q = 0; q < 16; ++q) acc[q] = 0.f;

    if (half == 0) {                            // self-loop term
        uint4 u = *(const uint4*)(g_h1s + rbase);
        fp8x16_acc(u, acc);
    }

    int beg = g_off[node];
    int cnt = g_ideg[node];
    const int* nb = g_csr + beg;
    for (int j = half; j < cnt; j += 2) {
        int s = nb[j];
        uint4 u = *(const uint4*)(g_h1s + (size_t)s * H + coff);
        fp8x16_acc(u, acc);
    }

    // combine half-warps
#pragma unroll
    for (int q = 0; q < 16; ++q)
        acc[q] += __shfl_xor_sync(0xffffffffu, acc[q], 16);

    if (half == 0) {
        float dv = g_dinv[node];
        __half2 h[8];
#pragma unroll
        for (int q = 0; q < 8; ++q)
            h[q] = __floats2half2_rn(acc[q * 2] * dv, acc[q * 2 + 1] * dv);
        *(uint4*)(g_z2 + rbase)     = ((uint4*)h)[0];
        *(uint4*)(g_z2 + rbase + 8) = ((uint4*)h)[1];
    }
}

// ======== tensor-core GEMM (mma.sync fp16, single pass) =====================
// A: [M, K] fp16 row-major.  Wt: [256, K] fp16 row-major.
// mode 0: C(fp8) = fp8( dinv[row] * relu(A@Wt^T + bias) )
// mode 1: red.add relu(A@Wt^T + bias) into gsum[batch[row]]  (mean-pool)
#define ST_A  0
#define ST_B  16384
#define STAGE 32768
#define GEMM_SMEM (2 * STAGE)   // 65536

__global__ void __launch_bounds__(256, 2)
gemm_tc(const __half* __restrict__ Af, const __half* __restrict__ Bf,
        const float* __restrict__ bias, const float* __restrict__ dinv,
        unsigned char* __restrict__ C, const int* __restrict__ batch,
        float* __restrict__ gsum, int M, int K, int mode)
{
    extern __shared__ __align__(128) char smem[];
    const uint32_t sb = smem_u32(smem);
    const int tid = threadIdx.x;
    const int wid = tid >> 5;
    const int lane = tid & 31;
    const int tile0 = blockIdx.x * 128;      // M block
    const int nb = blockIdx.y * 128;         // N block

    const int kcn = K >> 6;

    const int lrow   = tid >> 3;                     // 0..31
    const int dstx   = ((tid & 7) << 4) ^ ((lrow & 7) << 4);   // swizzled 16B chunk
    const int colelm = (tid & 7) << 3;               // source col (elements)

    const int warp_m = wid & 1;
    const int warp_n = wid >> 1;
    const int arow  = warp_m * 64 + (lane & 15);
    const int axor  = (lane & 7) << 4;
    const int ac8   = (lane >> 4) << 4;
    const int brow  = warp_n * 32 + (lane & 7) + ((lane & 16) >> 1);
    const int bxor  = (lane & 7) << 4;
    const int bc8   = ((lane >> 3) & 1) << 4;

    float acc[4][4][4];
#pragma unroll
    for (int i = 0; i < 4; ++i)
#pragma unroll
        for (int j = 0; j < 4; ++j)
#pragma unroll
            for (int q = 0; q < 4; ++q) acc[i][j][q] = 0.f;

    auto load_stage = [&](int kc, int st) {
        const int kofs = (kc << 6) + colelm;
        uint32_t base = sb + st * STAGE;
#pragma unroll
        for (int j = 0; j < 4; ++j) {
            int row = lrow + (j << 5);
            int gr = tile0 + row; if (gr >= M) gr = M - 1;
            uint32_t rb = base + row * 128 + dstx;
            cp16(rb + ST_A, Af + (size_t)gr * K + kofs);
            cp16(rb + ST_B, Bf + (size_t)(nb + row) * K + kofs);
        }
    };

    load_stage(0, 0);
    CP_COMMIT();

    for (int ch = 0; ch < kcn; ++ch) {
        int st = ch & 1;
        if (ch + 1 < kcn) {
            load_stage(ch + 1, st ^ 1);
            CP_COMMIT();
            CP_WAIT1();
        } else {
            CP_WAIT0();
        }
        __syncthreads();

        uint32_t Abase = sb + st * STAGE + ST_A;
        uint32_t Bbase = sb + st * STAGE + ST_B;
#pragma unroll
        for (int k16 = 0; k16 < 4; ++k16) {
            uint32_t a[4][4], b[2][4];
            int cA = ((k16 << 5) + ac8) ^ axor;
            uint32_t aaddr = Abase + arow * 128 + cA;
#pragma unroll
            for (int tm = 0; tm < 4; ++tm) ldm_x4(a[tm], aaddr + tm * 2048);
            int cB = ((k16 << 5) + bc8) ^ bxor;
            uint32_t baddr = Bbase + brow * 128 + cB;
#pragma unroll
            for (int t2 = 0; t2 < 2; ++t2) ldm_x4(b[t2], baddr + t2 * 2048);
#pragma unroll
            for (int tm = 0; tm < 4; ++tm)
#pragma unroll
                for (int tn = 0; tn < 4; ++tn)
                    mma16816(acc[tm][tn], a[tm], &b[tn >> 1][(tn & 1) * 2]);
        }
        __syncthreads();
    }

    // ---- epilogue
    const int mrow0 = tile0 + warp_m * 64 + (lane >> 2);
    const int ncol0 = nb + warp_n * 32 + (lane & 3) * 2;
#pragma unroll
    for (int tm = 0; tm < 4; ++tm) {
        int r0 = mrow0 + tm * 16;
        int r1 = r0 + 8;
#pragma unroll
        for (int tn = 0; tn < 4; ++tn) {
            int c = ncol0 + tn * 8;
            const float2 bb = *(const float2*)(bias + c);
            float v0 = fmaxf(acc[tm][tn][0] + bb.x, 0.f);
            float v1 = fmaxf(acc[tm][tn][1] + bb.y, 0.f);
            float v2 = fmaxf(acc[tm][tn][2] + bb.x, 0.f);
            float v3 = fmaxf(acc[tm][tn][3] + bb.y, 0.f);
            if (mode == 0) {
                if (r0 < M) {
                    float dv0 = dinv[r0];
                    __nv_fp8x2_storage_t s = __nv_cvt_float2_to_fp8x2(
                        make_float2(v0 * dv0, v1 * dv0), __NV_SATFINITE, __NV_E4M3);
                    *(unsigned short*)(C + (size_t)r0 * H + c) = s;
                }
                if (r1 < M) {
                    float dv1 = dinv[r1];
                    __nv_fp8x2_storage_t s = __nv_cvt_float2_to_fp8x2(
                        make_float2(v2 * dv1, v3 * dv1), __NV_SATFINITE, __NV_E4M3);
                    *(unsigned short*)(C + (size_t)r1 * H + c) = s;
                }
            } else {
                if (r0 < M) {
                    float* p = gsum + (size_t)batch[r0] * H + c;
                    asm volatile("red.global.add.v2.f32 [%0], {%1, %2};"
                                 :: "l"(p), "f"(v0), "f"(v1) : "memory");
                }
                if (r1 < M) {
                    float* p = gsum + (size_t)batch[r1] * H + c;
                    asm volatile("red.global.add.v2.f32 [%0], {%1, %2};"
                                 :: "l"(p), "f"(v2), "f"(v3) : "memory");
                }
            }
        }
    }
}

// ---------------- classifier: mean, g@Wc+bc, log_softmax(64) ----------------
__global__ void classify_kernel(const float* __restrict__ gsum, const float* __restrict__ gcnt,
                                const float* __restrict__ Wc, const float* __restrict__ bc,
                                float* __restrict__ out)
{
    int gid = blockIdx.x;
    int j = threadIdx.x;                       // 64 threads
    __shared__ float sg[H];
    __shared__ float red2[2];

    float inv = 1.0f / fmaxf(gcnt[gid], 1.0f);
    for (int c = j; c < H; c += 64) sg[c] = gsum[(size_t)gid * H + c] * inv;
    __syncthreads();

    float acc = bc[j];
#pragma unroll
    for (int c = 0; c < H; ++c)
        acc = fmaf(sg[c], Wc[c * 64 + j], acc);

    float m = acc;
#pragma unroll
    for (int o = 16; o; o >>= 1) m = fmaxf(m, __shfl_xor_sync(0xffffffffu, m, o));
    if ((j & 31) == 0) red2[j >> 5] = m;
    __syncthreads();
    m = fmaxf(red2[0], red2[1]);
    __syncthreads();

    float e = expf(acc - m);
    float s = e;
#pragma unroll
    for (int o = 16; o; o >>= 1) s += __shfl_xor_sync(0xffffffffu, s, o);
    if ((j & 31) == 0) red2[j >> 5] = s;
    __syncthreads();
    s = red2[0] + red2[1];

    out[(size_t)gid * 64 + j] = acc - m - logf(s);
}

// ---------------- launch ----------------
extern "C" void kernel_launch(void* const* d_in, const int* in_sizes, int n_in,
                              void* d_out, int out_size)
{
    const float* x     = (const float*)d_in[0];
    const int*   eidx  = (const int*)d_in[1];     // int32 (JAX canonicalized)
    const int*   batch = (const int*)d_in[2];
    const float* W1    = (const float*)d_in[3];
    const float* b1    = (const float*)d_in[4];
    const float* W2    = (const float*)d_in[5];
    const float* b2    = (const float*)d_in[6];
    const float* Wc    = (const float*)d_in[7];
    const float* bc    = (const float*)d_in[8];
    float*       out   = (float*)d_out;

    const int* src = eidx;
    const int* dst = eidx + N_EDGES;

    float *dinv, *gsum, *gcnt;
    __half *z1, *z2, *w1, *w2;
    unsigned char* h1s;
    cudaGetSymbolAddress((void**)&dinv, g_dinv);
    cudaGetSymbolAddress((void**)&gsum, g_gsum);
    cudaGetSymbolAddress((void**)&gcnt, g_gcnt);
    cudaGetSymbolAddress((void**)&z1,  g_z1);
    cudaGetSymbolAddress((void**)&h1s, g_h1s);
    cudaGetSymbolAddress((void**)&z2,  g_z2);
    cudaGetSymbolAddress((void**)&w1,  g_w1);
    cudaGetSymbolAddress((void**)&w2,  g_w2);

    cudaFuncSetAttribute(gemm_tc, cudaFuncAttributeMaxDynamicSharedMemorySize, GEMM_SMEM);

    // prep + CSR build
    zero_kernel<<<(N_GRAPHS * H) / 256, 256>>>();
    deg_kernel<<<(N_EDGES + 255) / 256, 256>>>(dst);
    scan1_kernel<<<SCAN_NBLK, 256>>>();
    scan2_kernel<<<1, 128>>>();
    scan3_kernel<<<(N_NODES + 255) / 256, 256>>>();
    fill_kernel<<<(N_EDGES + 255) / 256, 256>>>(src, dst);
    prep_kernel<<<(N_NODES + 255) / 256, 256>>>(batch);

    // operand conversions (convert_x needs dinv -> after prep)
    convert_x_kernel<<<(N_NODES * 128 / 4) / 256, 256>>>(x);
    split_w_kernel<<<(128 * 256 + 255) / 256, 256>>>(W1, w1, 128);
    split_w_kernel<<<(256 * 256 + 255) / 256, 256>>>(W2, w2, 256);

    const int ntiles = (N_NODES + 127) / 128;   // 782
    dim3 ggrid(ntiles, 2);                      // N blocks of 128
    const int agrid = N_NODES / 8;              // 12500

    // layer 1: aggregate xs first, then GEMM w/ relu+dinv+fp8 epilogue
    agg1_kernel<<<agrid, 256>>>();
    gemm_tc<<<ggrid, 256, GEMM_SMEM>>>(z1, w1, b1, dinv, h1s, nullptr, nullptr,
                                       N_NODES, 128, 0);

    // layer 2: aggregate fp8 h1s, then GEMM w/ relu + fused mean-pool epilogue
    agg2_kernel<<<agrid, 256>>>();
    gemm_tc<<<ggrid, 256, GEMM_SMEM>>>(z2, w2, b2, nullptr, nullptr, batch, gsum,
                                       N_NODES, 256, 1);

    // classifier + log_softmax
    classify_kernel<<<N_GRAPHS, 64>>>(gsum, gcnt, Wc, bc, out);
}

// round 13
// speedup vs baseline: 1.0277x; 1.0277x over previous
#include <cuda_runtime.h>
#include <cuda_fp16.h>
#include <math.h>
#include <stdint.h>

#define N_NODES  100000
#define N_EDGES  1600000
#define N_GRAPHS 2048
#define H        256

#define SCAN_NBLK ((N_NODES + 1023) / 1024)   // 98 blocks of 1024

// ---------------- scratch (device globals; no allocs allowed) ----------------
__device__ int   g_ideg[N_NODES];
__device__ int   g_off[N_NODES];
__device__ int   g_cursor[N_NODES];
__device__ int   g_csr[N_EDGES];
__device__ int   g_bsum[SCAN_NBLK];
__device__ int   g_bscan[SCAN_NBLK];
__device__ float g_dinv[N_NODES];
__device__ float g_gsum[N_GRAPHS * H];
__device__ float g_gcnt[N_GRAPHS];
// fp16 node features
__device__ __half g_xs[(size_t)N_NODES * 128];    // dinv * x          (gather src, L1)
__device__ __half g_z1[(size_t)N_NODES * 128];    // dinv*(sum xs)     (gemm1 A)
__device__ __half g_h1s[(size_t)N_NODES * H];     // dinv*relu(z1W1+b1) (gather src, L2)
__device__ __half g_z2[(size_t)N_NODES * H];      // dinv*(sum h1s)    (gemm2 A)
__device__ __half g_w1[256 * 128];
__device__ __half g_w2[256 * 256];

// ================= warp-MMA helpers (sm_80-class, compile for compute_103) ==
__device__ __forceinline__ uint32_t smem_u32(const void* p) {
    uint32_t a;
    asm("{ .reg .u64 t; cvta.to.shared.u64 t, %1; cvt.u32.u64 %0, t; }" : "=r"(a) : "l"(p));
    return a;
}
__device__ __forceinline__ void ldm_x4(uint32_t* r, uint32_t addr) {
    asm volatile("ldmatrix.sync.aligned.m8n8.x4.shared.b16 {%0,%1,%2,%3}, [%4];"
                 : "=r"(r[0]), "=r"(r[1]), "=r"(r[2]), "=r"(r[3]) : "r"(addr));
}
__device__ __forceinline__ void mma16816(float* d, const uint32_t* a, const uint32_t* b) {
    asm volatile("mma.sync.aligned.m16n8k16.row.col.f32.f16.f16.f32 "
                 "{%0,%1,%2,%3}, {%4,%5,%6,%7}, {%8,%9}, {%0,%1,%2,%3};"
                 : "+f"(d[0]), "+f"(d[1]), "+f"(d[2]), "+f"(d[3])
                 : "r"(a[0]), "r"(a[1]), "r"(a[2]), "r"(a[3]), "r"(b[0]), "r"(b[1]));
}
__device__ __forceinline__ void cp16(uint32_t dst, const void* src) {
    asm volatile("cp.async.ca.shared.global [%0], [%1], 16;" :: "r"(dst), "l"(src));
}
#define CP_COMMIT() asm volatile("cp.async.commit_group;" ::: "memory")
#define CP_WAIT1()  asm volatile("cp.async.wait_group 1;" ::: "memory")
#define CP_WAIT0()  asm volatile("cp.async.wait_group 0;" ::: "memory")

__device__ __forceinline__ void h8_acc(uint4 u, float* acc) {
    const __half2* hp = (const __half2*)&u;
#pragma unroll
    for (int q = 0; q < 4; ++q) {
        float2 f = __half22float2(hp[q]);
        acc[q * 2] += f.x; acc[q * 2 + 1] += f.y;
    }
}

// ---------------- prep kernels ----------------

__global__ void zero_kernel() {
    int i = blockIdx.x * blockDim.x + threadIdx.x;     // grid covers N_GRAPHS*H = 524288
    if (i < N_NODES) { g_ideg[i] = 0; g_cursor[i] = 0; }
    if (i < N_GRAPHS * H) g_gsum[i] = 0.f;
    if (i < N_GRAPHS)     g_gcnt[i] = 0.f;
}

__global__ void deg_kernel(const int* __restrict__ dst) {
    int e = blockIdx.x * blockDim.x + threadIdx.x;
    if (e < N_EDGES) atomicAdd(&g_ideg[dst[e]], 1);
}

__global__ void scan1_kernel() {
    __shared__ int sh[256];
    int tid = threadIdx.x;
    int base = blockIdx.x * 1024 + tid * 4;
    int v[4]; int s = 0;
#pragma unroll
    for (int k = 0; k < 4; ++k) {
        int i = base + k;
        v[k] = (i < N_NODES) ? g_ideg[i] : 0;
        s += v[k];
    }
    sh[tid] = s; __syncthreads();
#pragma unroll
    for (int o = 1; o < 256; o <<= 1) {
        int t = (tid >= o) ? sh[tid - o] : 0;
        __syncthreads(); sh[tid] += t; __syncthreads();
    }
    int run = sh[tid] - s;
#pragma unroll
    for (int k = 0; k < 4; ++k) {
        int i = base + k;
        if (i < N_NODES) g_off[i] = run;
        run += v[k];
    }
    if (tid == 255) g_bsum[blockIdx.x] = sh[255];
}

__global__ void scan2_kernel() {
    __shared__ int sh[128];
    int tid = threadIdx.x;
    int v = (tid < SCAN_NBLK) ? g_bsum[tid] : 0;
    sh[tid] = v; __syncthreads();
#pragma unroll
    for (int o = 1; o < 128; o <<= 1) {
        int t = (tid >= o) ? sh[tid - o] : 0;
        __syncthreads(); sh[tid] += t; __syncthreads();
    }
    if (tid < SCAN_NBLK) g_bscan[tid] = sh[tid] - v;
}

// scan finalize + degree-norm + graph-count (prep fused in)
__global__ void scan3_prep_kernel(const int* __restrict__ batch) {
    int i = blockIdx.x * blockDim.x + threadIdx.x;
    if (i < N_NODES) {
        g_off[i] += g_bscan[i >> 10];
        g_dinv[i] = rsqrtf((float)g_ideg[i] + 1.0f);   // +1 self-loop
        atomicAdd(&g_gcnt[batch[i]], 1.0f);
    }
}

__global__ void fill_kernel(const int* __restrict__ src, const int* __restrict__ dst) {
    int e = blockIdx.x * blockDim.x + threadIdx.x;
    if (e < N_EDGES) {
        int d = dst[e];
        int pos = g_off[d] + atomicAdd(&g_cursor[d], 1);
        g_csr[pos] = src[e];
    }
}

// xs = dinv[node] * x (fp16); one float4 per thread. Runs AFTER scan3_prep.
__global__ void convert_x_kernel(const float* __restrict__ x) {
    int i = blockIdx.x * blockDim.x + threadIdx.x;     // N_NODES*128/4 threads exactly
    float dv = g_dinv[i >> 5];
    float4 v = ((const float4*)x)[i];
    ((__half2*)g_xs)[i * 2 + 0] = __floats2half2_rn(v.x * dv, v.y * dv);
    ((__half2*)g_xs)[i * 2 + 1] = __floats2half2_rn(v.z * dv, v.w * dv);
}

// transpose W[K,256] -> Wt [256,K] fp16
__global__ void split_w_kernel(const float* __restrict__ W,
                               __half* __restrict__ T, int K) {
    int i = blockIdx.x * blockDim.x + threadIdx.x;     // K*256 threads
    if (i < K * 256) {
        int k = i >> 8;
        int n = i & 255;
        T[n * K + k] = __float2half_rn(W[i]);          // coalesced read
    }
}

// ---------------- layer-1 aggregation on xs (128 fp16 cols, 256 B rows) -----
// One warp per node; half-warps process alternating edges, unroll 2
// (4 gathers in flight per warp). z1 = dinv[d] * (sum + self).
__global__ void __launch_bounds__(256)
agg1_kernel()
{
    int warp = threadIdx.x >> 5;
    int lane = threadIdx.x & 31;
    int node = blockIdx.x * 8 + warp;          // grid.x = 12500, exact
    int half = lane >> 4;
    int coff = (lane & 15) * 8;                // 16 lanes x 8 halfs = 128 cols
    size_t rbase = (size_t)node * 128 + coff;

    float acc[8];
#pragma unroll
    for (int q = 0; q < 8; ++q) acc[q] = 0.f;

    if (half == 0) {                            // self-loop term: xs[d]
        uint4 u = *(const uint4*)(g_xs + rbase);
        h8_acc(u, acc);
    }

    int beg = g_off[node];
    int cnt = g_ideg[node];
    const int* nb = g_csr + beg;
    int j = half;
    for (; j + 2 < cnt; j += 4) {               // two edges per half-warp iter
        int s0 = nb[j], s1 = nb[j + 2];
        uint4 u0 = *(const uint4*)(g_xs + (size_t)s0 * 128 + coff);
        uint4 u1 = *(const uint4*)(g_xs + (size_t)s1 * 128 + coff);
        h8_acc(u0, acc);
        h8_acc(u1, acc);
    }
    if (j < cnt) {
        uint4 u = *(const uint4*)(g_xs + (size_t)nb[j] * 128 + coff);
        h8_acc(u, acc);
    }

    // combine half-warps (lane i <-> i^16 share coff)
#pragma unroll
    for (int q = 0; q < 8; ++q)
        acc[q] += __shfl_xor_sync(0xffffffffu, acc[q], 16);

    if (half == 0) {
        float dv = g_dinv[node];
        __half2 h[4];
#pragma unroll
        for (int q = 0; q < 4; ++q)
            h[q] = __floats2half2_rn(acc[q * 2] * dv, acc[q * 2 + 1] * dv);
        *(uint4*)(g_z1 + rbase) = *(uint4*)h;
    }
}

// ---------------- layer-2 aggregation on h1s (256 fp16 cols, 512 B rows) ----
// Full warp, lane covers 8 cols via uint4; unroll-4 for MLP.
__global__ void __launch_bounds__(256)
agg2_kernel()
{
    int warp = threadIdx.x >> 5;
    int lane = threadIdx.x & 31;
    int node = blockIdx.x * 8 + warp;          // grid.x = 12500
    int coff = lane * 8;
    size_t rbase = (size_t)node * H + coff;

    float acc[8];
#pragma unroll
    for (int q = 0; q < 8; ++q) acc[q] = 0.f;
    {
        uint4 u = *(const uint4*)(g_h1s + rbase);   // self-loop term
        h8_acc(u, acc);
    }

    int beg = g_off[node];
    int cnt = g_ideg[node];
    const int* nb = g_csr + beg;
    int j = 0;
    for (; j + 3 < cnt; j += 4) {
        int s0 = nb[j], s1 = nb[j + 1], s2 = nb[j + 2], s3 = nb[j + 3];
        uint4 u0 = *(const uint4*)(g_h1s + (size_t)s0 * H + coff);
        uint4 u1 = *(const uint4*)(g_h1s + (size_t)s1 * H + coff);
        uint4 u2 = *(const uint4*)(g_h1s + (size_t)s2 * H + coff);
        uint4 u3 = *(const uint4*)(g_h1s + (size_t)s3 * H + coff);
        h8_acc(u0, acc);
        h8_acc(u1, acc);
        h8_acc(u2, acc);
        h8_acc(u3, acc);
    }
    for (; j < cnt; ++j) {
        uint4 u = *(const uint4*)(g_h1s + (size_t)nb[j] * H + coff);
        h8_acc(u, acc);
    }

    float dv = g_dinv[node];
    __half2 h[4];
#pragma unroll
    for (int q = 0; q < 4; ++q)
        h[q] = __floats2half2_rn(acc[q * 2] * dv, acc[q * 2 + 1] * dv);
    *(uint4*)(g_z2 + rbase) = *(uint4*)h;
}

// ======== tensor-core GEMM (mma.sync fp16, single pass) =====================
// A: [M, K] fp16 row-major.  Wt: [256, K] fp16 row-major.
// mode 0: C = dinv[row] * relu(A@Wt^T + bias)  -> fp16 C
// mode 1: red.add relu(A@Wt^T + bias) into gsum[batch[row]]  (mean-pool)
#define ST_A  0
#define ST_B  16384
#define STAGE 32768
#define GEMM_SMEM (2 * STAGE)   // 65536

__global__ void __launch_bounds__(256, 2)
gemm_tc(const __half* __restrict__ Af, const __half* __restrict__ Bf,
        const float* __restrict__ bias, const float* __restrict__ dinv,
        __half* __restrict__ C, const int* __restrict__ batch,
        float* __restrict__ gsum, int M, int K, int mode)
{
    extern __shared__ __align__(128) char smem[];
    const uint32_t sb = smem_u32(smem);
    const int tid = threadIdx.x;
    const int wid = tid >> 5;
    const int lane = tid & 31;
    const int tile0 = blockIdx.x * 128;      // M block
    const int nb = blockIdx.y * 128;         // N block

    const int kcn = K >> 6;

    const int lrow   = tid >> 3;                     // 0..31
    const int dstx   = ((tid & 7) << 4) ^ ((lrow & 7) << 4);   // swizzled 16B chunk
    const int colelm = (tid & 7) << 3;               // source col (elements)

    const int warp_m = wid & 1;
    const int warp_n = wid >> 1;
    const int arow  = warp_m * 64 + (lane & 15);
    const int axor  = (lane & 7) << 4;
    const int ac8   = (lane >> 4) << 4;
    const int brow  = warp_n * 32 + (lane & 7) + ((lane & 16) >> 1);
    const int bxor  = (lane & 7) << 4;
    const int bc8   = ((lane >> 3) & 1) << 4;

    float acc[4][4][4];
#pragma unroll
    for (int i = 0; i < 4; ++i)
#pragma unroll
        for (int j = 0; j < 4; ++j)
#pragma unroll
            for (int q = 0; q < 4; ++q) acc[i][j][q] = 0.f;

    auto load_stage = [&](int kc, int st) {
        const int kofs = (kc << 6) + colelm;
        uint32_t base = sb + st * STAGE;
#pragma unroll
        for (int j = 0; j < 4; ++j) {
            int row = lrow + (j << 5);
            int gr = tile0 + row; if (gr >= M) gr = M - 1;
            uint32_t rb = base + row * 128 + dstx;
            cp16(rb + ST_A, Af + (size_t)gr * K + kofs);
            cp16(rb + ST_B, Bf + (size_t)(nb + row) * K + kofs);
        }
    };

    load_stage(0, 0);
    CP_COMMIT();

    for (int ch = 0; ch < kcn; ++ch) {
        int st = ch & 1;
        if (ch + 1 < kcn) {
            load_stage(ch + 1, st ^ 1);
            CP_COMMIT();
            CP_WAIT1();
        } else {
            CP_WAIT0();
        }
        __syncthreads();

        uint32_t Abase = sb + st * STAGE + ST_A;
        uint32_t Bbase = sb + st * STAGE + ST_B;
#pragma unroll
        for (int k16 = 0; k16 < 4; ++k16) {
            uint32_t a[4][4], b[2][4];
            int cA = ((k16 << 5) + ac8) ^ axor;
            uint32_t aaddr = Abase + arow * 128 + cA;
#pragma unroll
            for (int tm = 0; tm < 4; ++tm) ldm_x4(a[tm], aaddr + tm * 2048);
            int cB = ((k16 << 5) + bc8) ^ bxor;
            uint32_t baddr = Bbase + brow * 128 + cB;
#pragma unroll
            for (int t2 = 0; t2 < 2; ++t2) ldm_x4(b[t2], baddr + t2 * 2048);
#pragma unroll
            for (int tm = 0; tm < 4; ++tm)
#pragma unroll
                for (int tn = 0; tn < 4; ++tn)
                    mma16816(acc[tm][tn], a[tm], &b[tn >> 1][(tn & 1) * 2]);
        }
        __syncthreads();
    }

    // ---- epilogue
    const int mrow0 = tile0 + warp_m * 64 + (lane >> 2);
    const int ncol0 = nb + warp_n * 32 + (lane & 3) * 2;
#pragma unroll
    for (int tm = 0; tm < 4; ++tm) {
        int r0 = mrow0 + tm * 16;
        int r1 = r0 + 8;
#pragma unroll
        for (int tn = 0; tn < 4; ++tn) {
            int c = ncol0 + tn * 8;
            const float2 bb = *(const float2*)(bias + c);
            float v0 = fmaxf(acc[tm][tn][0] + bb.x, 0.f);
            float v1 = fmaxf(acc[tm][tn][1] + bb.y, 0.f);
            float v2 = fmaxf(acc[tm][tn][2] + bb.x, 0.f);
            float v3 = fmaxf(acc[tm][tn][3] + bb.y, 0.f);
            if (mode == 0) {
                if (r0 < M) {
                    float dv0 = dinv[r0];
                    *(__half2*)(C + (size_t)r0 * H + c) =
                        __floats2half2_rn(v0 * dv0, v1 * dv0);
                }
                if (r1 < M) {
                    float dv1 = dinv[r1];
                    *(__half2*)(C + (size_t)r1 * H + c) =
                        __floats2half2_rn(v2 * dv1, v3 * dv1);
                }
            } else {
                if (r0 < M) {
                    float* p = gsum + (size_t)batch[r0] * H + c;
                    asm volatile("red.global.add.v2.f32 [%0], {%1, %2};"
                                 :: "l"(p), "f"(v0), "f"(v1) : "memory");
                }
                if (r1 < M) {
                    float* p = gsum + (size_t)batch[r1] * H + c;
                    asm volatile("red.global.add.v2.f32 [%0], {%1, %2};"
                                 :: "l"(p), "f"(v2), "f"(v3) : "memory");
                }
            }
        }
    }
}

// ---------------- classifier: mean, g@Wc+bc, log_softmax(64) ----------------
__global__ void classify_kernel(const float* __restrict__ gsum, const float* __restrict__ gcnt,
                                const float* __restrict__ Wc, const float* __restrict__ bc,
                                float* __restrict__ out)
{
    int gid = blockIdx.x;
    int j = threadIdx.x;                       // 64 threads
    __shared__ float sg[H];
    __shared__ float red2[2];

    float inv = 1.0f / fmaxf(gcnt[gid], 1.0f);
    for (int c = j; c < H; c += 64) sg[c] = gsum[(size_t)gid * H + c] * inv;
    __syncthreads();

    float acc = bc[j];
#pragma unroll
    for (int c = 0; c < H; ++c)
        acc = fmaf(sg[c], Wc[c * 64 + j], acc);

    float m = acc;
#pragma unroll
    for (int o = 16; o; o >>= 1) m = fmaxf(m, __shfl_xor_sync(0xffffffffu, m, o));
    if ((j & 31) == 0) red2[j >> 5] = m;
    __syncthreads();
    m = fmaxf(red2[0], red2[1]);
    __syncthreads();

    float e = expf(acc - m);
    float s = e;
#pragma unroll
    for (int o = 16; o; o >>= 1) s += __shfl_xor_sync(0xffffffffu, s, o);
    if ((j & 31) == 0) red2[j >> 5] = s;
    __syncthreads();
    s = red2[0] + red2[1];

    out[(size_t)gid * 64 + j] = acc - m - logf(s);
}

// ---------------- launch ----------------
extern "C" void kernel_launch(void* const* d_in, const int* in_sizes, int n_in,
                              void* d_out, int out_size)
{
    const float* x     = (const float*)d_in[0];
    const int*   eidx  = (const int*)d_in[1];     // int32 (JAX canonicalized)
    const int*   batch = (const int*)d_in[2];
    const float* W1    = (const float*)d_in[3];
    const float* b1    = (const float*)d_in[4];
    const float* W2    = (const float*)d_in[5];
    const float* b2    = (const float*)d_in[6];
    const float* Wc    = (const float*)d_in[7];
    const float* bc    = (const float*)d_in[8];
    float*       out   = (float*)d_out;

    const int* src = eidx;
    const int* dst = eidx + N_EDGES;

    float *dinv, *gsum, *gcnt;
    __half *z1, *h1s, *z2, *w1, *w2;
    cudaGetSymbolAddress((void**)&dinv, g_dinv);
    cudaGetSymbolAddress((void**)&gsum, g_gsum);
    cudaGetSymbolAddress((void**)&gcnt, g_gcnt);
    cudaGetSymbolAddress((void**)&z1,  g_z1);
    cudaGetSymbolAddress((void**)&h1s, g_h1s);
    cudaGetSymbolAddress((void**)&z2,  g_z2);
    cudaGetSymbolAddress((void**)&w1,  g_w1);
    cudaGetSymbolAddress((void**)&w2,  g_w2);

    cudaFuncSetAttribute(gemm_tc, cudaFuncAttributeMaxDynamicSharedMemorySize, GEMM_SMEM);

    // weight transposes first (no deps; also rotates ncu's fixed capture slot)
    split_w_kernel<<<(128 * 256 + 255) / 256, 256>>>(W1, w1, 128);
    split_w_kernel<<<(256 * 256 + 255) / 256, 256>>>(W2, w2, 256);

    // prep + CSR build
    zero_kernel<<<(N_GRAPHS * H) / 256, 256>>>();
    deg_kernel<<<(N_EDGES + 255) / 256, 256>>>(dst);
    scan1_kernel<<<SCAN_NBLK, 256>>>();
    scan2_kernel<<<1, 128>>>();
    scan3_prep_kernel<<<(N_NODES + 255) / 256, 256>>>(batch);
    fill_kernel<<<(N_EDGES + 255) / 256, 256>>>(src, dst);
    convert_x_kernel<<<(N_NODES * 128 / 4) / 256, 256>>>(x);

    const int ntiles = (N_NODES + 127) / 128;   // 782
    dim3 ggrid(ntiles, 2);                      // N blocks of 128
    const int agrid = N_NODES / 8;              // 12500

    // layer 1: aggregate xs first, then GEMM w/ relu+dinv epilogue
    agg1_kernel<<<agrid, 256>>>();
    gemm_tc<<<ggrid, 256, GEMM_SMEM>>>(z1, w1, b1, dinv, h1s, nullptr, nullptr,
                                       N_NODES, 128, 0);

    // layer 2: aggregate h1s, then GEMM w/ relu + fused mean-pool epilogue
    agg2_kernel<<<agrid, 256>>>();
    gemm_tc<<<ggrid, 256, GEMM_SMEM>>>(z2, w2, b2, nullptr, nullptr, batch, gsum,
                                       N_NODES, 256, 1);

    // classifier + log_softmax
    classify_kernel<<<N_GRAPHS, 64>>>(gsum, gcnt, Wc, bc, out);
}

// round 14
// speedup vs baseline: 1.1186x; 1.0885x over previous
#include <cuda_runtime.h>
#include <cuda_fp16.h>
#include <math.h>
#include <stdint.h>

#define N_NODES  100000
#define N_EDGES  1600000
#define N_GRAPHS 2048
#define H        256

#define SCAN_NBLK ((N_NODES + 1023) / 1024)   // 98 blocks of 1024

// ---------------- scratch (device globals; no allocs allowed) ----------------
__device__ int   g_ideg[N_NODES];
__device__ int   g_off[N_NODES];
__device__ int   g_cursor[N_NODES];
__device__ int   g_csr[N_EDGES];
__device__ int   g_bsum[SCAN_NBLK];
__device__ int   g_bscan[SCAN_NBLK];
__device__ float g_dinv[N_NODES];
__device__ float g_gsum[N_GRAPHS * H];
__device__ float g_gcnt[N_GRAPHS];
// fp16 node features
__device__ __half g_xs[(size_t)N_NODES * 128];    // dinv * x          (gather src, L1)
__device__ __half g_z1[(size_t)N_NODES * 128];    // dinv*(sum xs)     (gemm1 A)
__device__ __half g_h1s[(size_t)N_NODES * H];     // dinv*relu(z1W1+b1) (gather src, L2)
__device__ __half g_z2[(size_t)N_NODES * H];      // dinv*(sum h1s)    (gemm2 A)
__device__ __half g_w1[256 * 128];
__device__ __half g_w2[256 * 256];

// ================= warp-MMA helpers (sm_80-class, compile for compute_103) ==
__device__ __forceinline__ uint32_t smem_u32(const void* p) {
    uint32_t a;
    asm("{ .reg .u64 t; cvta.to.shared.u64 t, %1; cvt.u32.u64 %0, t; }" : "=r"(a) : "l"(p));
    return a;
}
__device__ __forceinline__ void ldm_x4(uint32_t* r, uint32_t addr) {
    asm volatile("ldmatrix.sync.aligned.m8n8.x4.shared.b16 {%0,%1,%2,%3}, [%4];"
                 : "=r"(r[0]), "=r"(r[1]), "=r"(r[2]), "=r"(r[3]) : "r"(addr));
}
__device__ __forceinline__ void mma16816(float* d, const uint32_t* a, const uint32_t* b) {
    asm volatile("mma.sync.aligned.m16n8k16.row.col.f32.f16.f16.f32 "
                 "{%0,%1,%2,%3}, {%4,%5,%6,%7}, {%8,%9}, {%0,%1,%2,%3};"
                 : "+f"(d[0]), "+f"(d[1]), "+f"(d[2]), "+f"(d[3])
                 : "r"(a[0]), "r"(a[1]), "r"(a[2]), "r"(a[3]), "r"(b[0]), "r"(b[1]));
}
__device__ __forceinline__ void cp16(uint32_t dst, const void* src) {
    asm volatile("cp.async.ca.shared.global [%0], [%1], 16;" :: "r"(dst), "l"(src));
}
#define CP_COMMIT() asm volatile("cp.async.commit_group;" ::: "memory")
#define CP_WAIT1()  asm volatile("cp.async.wait_group 1;" ::: "memory")
#define CP_WAIT0()  asm volatile("cp.async.wait_group 0;" ::: "memory")

// packed fp16 accumulate: 4 HADD2 per uint4 (vs 16 cvt+fadd)
__device__ __forceinline__ void h2_acc(uint4 u, __half2* acc) {
    const __half2* hp = (const __half2*)&u;
#pragma unroll
    for (int q = 0; q < 4; ++q) acc[q] = __hadd2(acc[q], hp[q]);
}

// ---------------- prep kernels ----------------

__global__ void zero_kernel() {
    int i = blockIdx.x * blockDim.x + threadIdx.x;     // grid covers N_GRAPHS*H = 524288
    if (i < N_NODES)      g_ideg[i] = 0;
    if (i < N_GRAPHS * H) g_gsum[i] = 0.f;
    if (i < N_GRAPHS)     g_gcnt[i] = 0.f;
}

__global__ void deg_kernel(const int* __restrict__ dst) {
    int e = blockIdx.x * blockDim.x + threadIdx.x;
    if (e < N_EDGES) atomicAdd(&g_ideg[dst[e]], 1);
}

__global__ void scan1_kernel() {
    __shared__ int sh[256];
    int tid = threadIdx.x;
    int base = blockIdx.x * 1024 + tid * 4;
    int v[4]; int s = 0;
#pragma unroll
    for (int k = 0; k < 4; ++k) {
        int i = base + k;
        v[k] = (i < N_NODES) ? g_ideg[i] : 0;
        s += v[k];
    }
    sh[tid] = s; __syncthreads();
#pragma unroll
    for (int o = 1; o < 256; o <<= 1) {
        int t = (tid >= o) ? sh[tid - o] : 0;
        __syncthreads(); sh[tid] += t; __syncthreads();
    }
    int run = sh[tid] - s;
#pragma unroll
    for (int k = 0; k < 4; ++k) {
        int i = base + k;
        if (i < N_NODES) g_off[i] = run;
        run += v[k];
    }
    if (tid == 255) g_bsum[blockIdx.x] = sh[255];
}

__global__ void scan2_kernel() {
    __shared__ int sh[128];
    int tid = threadIdx.x;
    int v = (tid < SCAN_NBLK) ? g_bsum[tid] : 0;
    sh[tid] = v; __syncthreads();
#pragma unroll
    for (int o = 1; o < 128; o <<= 1) {
        int t = (tid >= o) ? sh[tid - o] : 0;
        __syncthreads(); sh[tid] += t; __syncthreads();
    }
    if (tid < SCAN_NBLK) g_bscan[tid] = sh[tid] - v;
}

// scan finalize + cursor init + degree-norm + graph-count
__global__ void scan3_prep_kernel(const int* __restrict__ batch) {
    int i = blockIdx.x * blockDim.x + threadIdx.x;
    if (i < N_NODES) {
        g_off[i] += g_bscan[i >> 10];
        g_cursor[i] = 0;
        g_dinv[i] = rsqrtf((float)g_ideg[i] + 1.0f);   // +1 self-loop
        atomicAdd(&g_gcnt[batch[i]], 1.0f);
    }
}

__global__ void fill_kernel(const int* __restrict__ src, const int* __restrict__ dst) {
    int e = blockIdx.x * blockDim.x + threadIdx.x;
    if (e < N_EDGES) {
        int d = dst[e];
        int pos = g_off[d] + atomicAdd(&g_cursor[d], 1);
        g_csr[pos] = src[e];
    }
}

// xs = dinv[node] * x (fp16); one float4 per thread. Runs AFTER scan3_prep.
__global__ void convert_x_kernel(const float* __restrict__ x) {
    int i = blockIdx.x * blockDim.x + threadIdx.x;     // N_NODES*128/4 threads exactly
    float dv = g_dinv[i >> 5];
    float4 v = ((const float4*)x)[i];
    ((__half2*)g_xs)[i * 2 + 0] = __floats2half2_rn(v.x * dv, v.y * dv);
    ((__half2*)g_xs)[i * 2 + 1] = __floats2half2_rn(v.z * dv, v.w * dv);
}

// transpose W[K,256] -> Wt [256,K] fp16
__global__ void split_w_kernel(const float* __restrict__ W,
                               __half* __restrict__ T, int K) {
    int i = blockIdx.x * blockDim.x + threadIdx.x;     // K*256 threads
    if (i < K * 256) {
        int k = i >> 8;
        int n = i & 255;
        T[n * K + k] = __float2half_rn(W[i]);          // coalesced read
    }
}

// ---------------- layer-1 aggregation on xs (128 fp16 cols, 256 B rows) -----
// One warp per node; half-warps process alternating edges, unroll 2
// (4 gathers in flight per warp). Packed half2 accumulation.
__global__ void __launch_bounds__(256)
agg1_kernel()
{
    int warp = threadIdx.x >> 5;
    int lane = threadIdx.x & 31;
    int node = blockIdx.x * 8 + warp;          // grid.x = 12500, exact
    int half = lane >> 4;
    int coff = (lane & 15) * 8;                // 16 lanes x 8 halfs = 128 cols
    size_t rbase = (size_t)node * 128 + coff;

    __half2 acc[4];
#pragma unroll
    for (int q = 0; q < 4; ++q) acc[q] = __halves2half2(__ushort_as_half(0), __ushort_as_half(0));

    if (half == 0) {                            // self-loop term: xs[d]
        uint4 u = *(const uint4*)(g_xs + rbase);
        h2_acc(u, acc);
    }

    int beg = g_off[node];
    int cnt = g_ideg[node];
    const int* nb = g_csr + beg;
    int j = half;
    for (; j + 2 < cnt; j += 4) {               // two edges per half-warp iter
        int s0 = nb[j], s1 = nb[j + 2];
        uint4 u0 = *(const uint4*)(g_xs + (size_t)s0 * 128 + coff);
        uint4 u1 = *(const uint4*)(g_xs + (size_t)s1 * 128 + coff);
        h2_acc(u0, acc);
        h2_acc(u1, acc);
    }
    if (j < cnt) {
        uint4 u = *(const uint4*)(g_xs + (size_t)nb[j] * 128 + coff);
        h2_acc(u, acc);
    }

    // combine half-warps on packed registers (lane i <-> i^16 share coff)
#pragma unroll
    for (int q = 0; q < 4; ++q) {
        uint32_t r = __shfl_xor_sync(0xffffffffu, *(uint32_t*)&acc[q], 16);
        acc[q] = __hadd2(acc[q], *(__half2*)&r);
    }

    if (half == 0) {
        float dv = g_dinv[node];
        __half2 h[4];
#pragma unroll
        for (int q = 0; q < 4; ++q) {
            float2 f = __half22float2(acc[q]);
            h[q] = __floats2half2_rn(f.x * dv, f.y * dv);
        }
        *(uint4*)(g_z1 + rbase) = *(uint4*)h;
    }
}

// ---------------- layer-2 aggregation on h1s (256 fp16 cols, 512 B rows) ----
// Full warp, lane covers 8 cols via uint4; unroll-4, packed half2 accumulation.
__global__ void __launch_bounds__(256)
agg2_kernel()
{
    int warp = threadIdx.x >> 5;
    int lane = threadIdx.x & 31;
    int node = blockIdx.x * 8 + warp;          // grid.x = 12500
    int coff = lane * 8;
    size_t rbase = (size_t)node * H + coff;

    __half2 acc[4];
    {
        uint4 u = *(const uint4*)(g_h1s + rbase);   // self-loop term
        const __half2* hp = (const __half2*)&u;
#pragma unroll
        for (int q = 0; q < 4; ++q) acc[q] = hp[q];
    }

    int beg = g_off[node];
    int cnt = g_ideg[node];
    const int* nb = g_csr + beg;
    int j = 0;
    for (; j + 3 < cnt; j += 4) {
        int s0 = nb[j], s1 = nb[j + 1], s2 = nb[j + 2], s3 = nb[j + 3];
        uint4 u0 = *(const uint4*)(g_h1s + (size_t)s0 * H + coff);
        uint4 u1 = *(const uint4*)(g_h1s + (size_t)s1 * H + coff);
        uint4 u2 = *(const uint4*)(g_h1s + (size_t)s2 * H + coff);
        uint4 u3 = *(const uint4*)(g_h1s + (size_t)s3 * H + coff);
        h2_acc(u0, acc);
        h2_acc(u1, acc);
        h2_acc(u2, acc);
        h2_acc(u3, acc);
    }
    for (; j < cnt; ++j) {
        uint4 u = *(const uint4*)(g_h1s + (size_t)nb[j] * H + coff);
        h2_acc(u, acc);
    }

    float dv = g_dinv[node];
    __half2 h[4];
#pragma unroll
    for (int q = 0; q < 4; ++q) {
        float2 f = __half22float2(acc[q]);
        h[q] = __floats2half2_rn(f.x * dv, f.y * dv);
    }
    *(uint4*)(g_z2 + rbase) = *(uint4*)h;
}

// ======== tensor-core GEMM (mma.sync fp16, single pass) =====================
// A: [M, K] fp16 row-major.  Wt: [256, K] fp16 row-major.
// mode 0: C = dinv[row] * relu(A@Wt^T + bias)  -> fp16 C
// mode 1: red.add relu(A@Wt^T + bias) into gsum[batch[row]]  (mean-pool)
#define ST_A  0
#define ST_B  16384
#define STAGE 32768
#define GEMM_SMEM (2 * STAGE)   // 65536

__global__ void __launch_bounds__(256, 2)
gemm_tc(const __half* __restrict__ Af, const __half* __restrict__ Bf,
        const float* __restrict__ bias, const float* __restrict__ dinv,
        __half* __restrict__ C, const int* __restrict__ batch,
        float* __restrict__ gsum, int M, int K, int mode)
{
    extern __shared__ __align__(128) char smem[];
    const uint32_t sb = smem_u32(smem);
    const int tid = threadIdx.x;
    const int wid = tid >> 5;
    const int lane = tid & 31;
    const int tile0 = blockIdx.x * 128;      // M block
    const int nb = blockIdx.y * 128;         // N block

    const int kcn = K >> 6;

    const int lrow   = tid >> 3;                     // 0..31
    const int dstx   = ((tid & 7) << 4) ^ ((lrow & 7) << 4);   // swizzled 16B chunk
    const int colelm = (tid & 7) << 3;               // source col (elements)

    const int warp_m = wid & 1;
    const int warp_n = wid >> 1;
    const int arow  = warp_m * 64 + (lane & 15);
    const int axor  = (lane & 7) << 4;
    const int ac8   = (lane >> 4) << 4;
    const int brow  = warp_n * 32 + (lane & 7) + ((lane & 16) >> 1);
    const int bxor  = (lane & 7) << 4;
    const int bc8   = ((lane >> 3) & 1) << 4;

    float acc[4][4][4];
#pragma unroll
    for (int i = 0; i < 4; ++i)
#pragma unroll
        for (int j = 0; j < 4; ++j)
#pragma unroll
            for (int q = 0; q < 4; ++q) acc[i][j][q] = 0.f;

    auto load_stage = [&](int kc, int st) {
        const int kofs = (kc << 6) + colelm;
        uint32_t base = sb + st * STAGE;
#pragma unroll
        for (int j = 0; j < 4; ++j) {
            int row = lrow + (j << 5);
            int gr = tile0 + row; if (gr >= M) gr = M - 1;
            uint32_t rb = base + row * 128 + dstx;
            cp16(rb + ST_A, Af + (size_t)gr * K + kofs);
            cp16(rb + ST_B, Bf + (size_t)(nb + row) * K + kofs);
        }
    };

    load_stage(0, 0);
    CP_COMMIT();

    for (int ch = 0; ch < kcn; ++ch) {
        int st = ch & 1;
        if (ch + 1 < kcn) {
            load_stage(ch + 1, st ^ 1);
            CP_COMMIT();
            CP_WAIT1();
        } else {
            CP_WAIT0();
        }
        __syncthreads();

        uint32_t Abase = sb + st * STAGE + ST_A;
        uint32_t Bbase = sb + st * STAGE + ST_B;
#pragma unroll
        for (int k16 = 0; k16 < 4; ++k16) {
            uint32_t a[4][4], b[2][4];
            int cA = ((k16 << 5) + ac8) ^ axor;
            uint32_t aaddr = Abase + arow * 128 + cA;
#pragma unroll
            for (int tm = 0; tm < 4; ++tm) ldm_x4(a[tm], aaddr + tm * 2048);
            int cB = ((k16 << 5) + bc8) ^ bxor;
            uint32_t baddr = Bbase + brow * 128 + cB;
#pragma unroll
            for (int t2 = 0; t2 < 2; ++t2) ldm_x4(b[t2], baddr + t2 * 2048);
#pragma unroll
            for (int tm = 0; tm < 4; ++tm)
#pragma unroll
                for (int tn = 0; tn < 4; ++tn)
                    mma16816(acc[tm][tn], a[tm], &b[tn >> 1][(tn & 1) * 2]);
        }
        __syncthreads();
    }

    // ---- epilogue
    const int mrow0 = tile0 + warp_m * 64 + (lane >> 2);
    const int ncol0 = nb + warp_n * 32 + (lane & 3) * 2;
#pragma unroll
    for (int tm = 0; tm < 4; ++tm) {
        int r0 = mrow0 + tm * 16;
        int r1 = r0 + 8;
#pragma unroll
        for (int tn = 0; tn < 4; ++tn) {
            int c = ncol0 + tn * 8;
            const float2 bb = *(const float2*)(bias + c);
            float v0 = fmaxf(acc[tm][tn][0] + bb.x, 0.f);
            float v1 = fmaxf(acc[tm][tn][1] + bb.y, 0.f);
            float v2 = fmaxf(acc[tm][tn][2] + bb.x, 0.f);
            float v3 = fmaxf(acc[tm][tn][3] + bb.y, 0.f);
            if (mode == 0) {
                if (r0 < M) {
                    float dv0 = dinv[r0];
                    *(__half2*)(C + (size_t)r0 * H + c) =
                        __floats2half2_rn(v0 * dv0, v1 * dv0);
                }
                if (r1 < M) {
                    float dv1 = dinv[r1];
                    *(__half2*)(C + (size_t)r1 * H + c) =
                        __floats2half2_rn(v2 * dv1, v3 * dv1);
                }
            } else {
                if (r0 < M) {
                    float* p = gsum + (size_t)batch[r0] * H + c;
                    asm volatile("red.global.add.v2.f32 [%0], {%1, %2};"
                                 :: "l"(p), "f"(v0), "f"(v1) : "memory");
                }
                if (r1 < M) {
                    float* p = gsum + (size_t)batch[r1] * H + c;
                    asm volatile("red.global.add.v2.f32 [%0], {%1, %2};"
                                 :: "l"(p), "f"(v2), "f"(v3) : "memory");
                }
            }
        }
    }
}

// ---------------- classifier: mean, g@Wc+bc, log_softmax(64) ----------------
__global__ void classify_kernel(const float* __restrict__ gsum, const float* __restrict__ gcnt,
                                const float* __restrict__ Wc, const float* __restrict__ bc,
                                float* __restrict__ out)
{
    int gid = blockIdx.x;
    int j = threadIdx.x;                       // 64 threads
    __shared__ float sg[H];
    __shared__ float red2[2];

    float inv = 1.0f / fmaxf(gcnt[gid], 1.0f);
    for (int c = j; c < H; c += 64) sg[c] = gsum[(size_t)gid * H + c] * inv;
    __syncthreads();

    float acc = bc[j];
#pragma unroll
    for (int c = 0; c < H; ++c)
        acc = fmaf(sg[c], Wc[c * 64 + j], acc);

    float m = acc;
#pragma unroll
    for (int o = 16; o; o >>= 1) m = fmaxf(m, __shfl_xor_sync(0xffffffffu, m, o));
    if ((j & 31) == 0) red2[j >> 5] = m;
    __syncthreads();
    m = fmaxf(red2[0], red2[1]);
    __syncthreads();

    float e = expf(acc - m);
    float s = e;
#pragma unroll
    for (int o = 16; o; o >>= 1) s += __shfl_xor_sync(0xffffffffu, s, o);
    if ((j & 31) == 0) red2[j >> 5] = s;
    __syncthreads();
    s = red2[0] + red2[1];

    out[(size_t)gid * 64 + j] = acc - m - logf(s);
}

// ---------------- launch ----------------
extern "C" void kernel_launch(void* const* d_in, const int* in_sizes, int n_in,
                              void* d_out, int out_size)
{
    const float* x     = (const float*)d_in[0];
    const int*   eidx  = (const int*)d_in[1];     // int32 (JAX canonicalized)
    const int*   batch = (const int*)d_in[2];
    const float* W1    = (const float*)d_in[3];
    const float* b1    = (const float*)d_in[4];
    const float* W2    = (const float*)d_in[5];
    const float* b2    = (const float*)d_in[6];
    const float* Wc    = (const float*)d_in[7];
    const float* bc    = (const float*)d_in[8];
    float*       out   = (float*)d_out;

    const int* src = eidx;
    const int* dst = eidx + N_EDGES;

    float *dinv, *gsum, *gcnt;
    __half *z1, *h1s, *z2, *w1, *w2;
    cudaGetSymbolAddress((void**)&dinv, g_dinv);
    cudaGetSymbolAddress((void**)&gsum, g_gsum);
    cudaGetSymbolAddress((void**)&gcnt, g_gcnt);
    cudaGetSymbolAddress((void**)&z1,  g_z1);
    cudaGetSymbolAddress((void**)&h1s, g_h1s);
    cudaGetSymbolAddress((void**)&z2,  g_z2);
    cudaGetSymbolAddress((void**)&w1,  g_w1);
    cudaGetSymbolAddress((void**)&w2,  g_w2);

    cudaFuncSetAttribute(gemm_tc, cudaFuncAttributeMaxDynamicSharedMemorySize, GEMM_SMEM);

    // weight transposes first (no deps)
    split_w_kernel<<<(128 * 256 + 255) / 256, 256>>>(W1, w1, 128);
    split_w_kernel<<<(256 * 256 + 255) / 256, 256>>>(W2, w2, 256);

    // prep + CSR build
    zero_kernel<<<(N_GRAPHS * H) / 256, 256>>>();
    deg_kernel<<<(N_EDGES + 255) / 256, 256>>>(dst);
    scan1_kernel<<<SCAN_NBLK, 256>>>();
    scan2_kernel<<<1, 128>>>();
    scan3_prep_kernel<<<(N_NODES + 255) / 256, 256>>>(batch);
    fill_kernel<<<(N_EDGES + 255) / 256, 256>>>(src, dst);
    convert_x_kernel<<<(N_NODES * 128 / 4) / 256, 256>>>(x);

    const int ntiles = (N_NODES + 127) / 128;   // 782
    dim3 ggrid(ntiles, 2);                      // N blocks of 128
    const int agrid = N_NODES / 8;              // 12500

    // layer 1: aggregate xs first, then GEMM w/ relu+dinv epilogue
    agg1_kernel<<<agrid, 256>>>();
    gemm_tc<<<ggrid, 256, GEMM_SMEM>>>(z1, w1, b1, dinv, h1s, nullptr, nullptr,
                                       N_NODES, 128, 0);

    // layer 2: aggregate h1s, then GEMM w/ relu + fused mean-pool epilogue
    agg2_kernel<<<agrid, 256>>>();
    gemm_tc<<<ggrid, 256, GEMM_SMEM>>>(z2, w2, b2, nullptr, nullptr, batch, gsum,
                                       N_NODES, 256, 1);

    // classifier + log_softmax
    classify_kernel<<<N_GRAPHS, 64>>>(gsum, gcnt, Wc, bc, out);
}

// round 15
// speedup vs baseline: 1.1302x; 1.0104x over previous
#include <cuda_runtime.h>
#include <cuda_fp16.h>
#include <cuda_fp8.h>
#include <math.h>
#include <stdint.h>

#define N_NODES  100000
#define N_EDGES  1600000
#define N_GRAPHS 2048
#define H        256

#define SCAN_NBLK ((N_NODES + 1023) / 1024)   // 98 blocks of 1024

// ---------------- scratch (device globals; no allocs allowed) ----------------
__device__ int   g_ideg[N_NODES];
__device__ int   g_off[N_NODES + 1];          // exclusive scan + sentinel
__device__ int   g_csr[N_EDGES];
__device__ int   g_bsum[SCAN_NBLK];
__device__ float g_dinv[N_NODES];
__device__ float g_gsum[N_GRAPHS * H];
__device__ float g_gcnt[N_GRAPHS];
// node features
__device__ __half g_xs[(size_t)N_NODES * 128];        // dinv * x (fp16, gather L1)
__device__ __half g_z1[(size_t)N_NODES * 128];        // gemm1 A (fp16)
__device__ unsigned char g_h1s[(size_t)N_NODES * H];  // dinv*relu(...) fp8 (gather L2)
__device__ __half g_z2[(size_t)N_NODES * H];          // gemm2 A (fp16)
__device__ __half g_w1[256 * 128];
__device__ __half g_w2[256 * 256];

// ================= warp-MMA helpers (sm_80-class, compile for compute_103) ==
__device__ __forceinline__ uint32_t smem_u32(const void* p) {
    uint32_t a;
    asm("{ .reg .u64 t; cvta.to.shared.u64 t, %1; cvt.u32.u64 %0, t; }" : "=r"(a) : "l"(p));
    return a;
}
__device__ __forceinline__ void ldm_x4(uint32_t* r, uint32_t addr) {
    asm volatile("ldmatrix.sync.aligned.m8n8.x4.shared.b16 {%0,%1,%2,%3}, [%4];"
                 : "=r"(r[0]), "=r"(r[1]), "=r"(r[2]), "=r"(r[3]) : "r"(addr));
}
__device__ __forceinline__ void mma16816(float* d, const uint32_t* a, const uint32_t* b) {
    asm volatile("mma.sync.aligned.m16n8k16.row.col.f32.f16.f16.f32 "
                 "{%0,%1,%2,%3}, {%4,%5,%6,%7}, {%8,%9}, {%0,%1,%2,%3};"
                 : "+f"(d[0]), "+f"(d[1]), "+f"(d[2]), "+f"(d[3])
                 : "r"(a[0]), "r"(a[1]), "r"(a[2]), "r"(a[3]), "r"(b[0]), "r"(b[1]));
}
__device__ __forceinline__ void cp16(uint32_t dst, const void* src) {
    asm volatile("cp.async.ca.shared.global [%0], [%1], 16;" :: "r"(dst), "l"(src));
}
#define CP_COMMIT() asm volatile("cp.async.commit_group;" ::: "memory")
#define CP_WAIT1()  asm volatile("cp.async.wait_group 1;" ::: "memory")
#define CP_WAIT0()  asm volatile("cp.async.wait_group 0;" ::: "memory")

// packed fp16 accumulate: 4 HADD2 per uint4
__device__ __forceinline__ void h2_acc(uint4 u, __half2* acc) {
    const __half2* hp = (const __half2*)&u;
#pragma unroll
    for (int q = 0; q < 4; ++q) acc[q] = __hadd2(acc[q], hp[q]);
}
// fp8 accumulate: 16 e4m3 values (uint4) -> 8 cvt + 8 HADD2 into half2[8]
__device__ __forceinline__ void f8_acc(uint4 u, __half2* acc) {
    const __nv_fp8x2_storage_t* p = (const __nv_fp8x2_storage_t*)&u;
#pragma unroll
    for (int q = 0; q < 8; ++q) {
        __half2_raw hr = __nv_cvt_fp8x2_to_halfraw2(p[q], __NV_E4M3);
        acc[q] = __hadd2(acc[q], *(__half2*)&hr);
    }
}

// ---------------- prep kernels ----------------

__global__ void zero_kernel() {
    int i = blockIdx.x * blockDim.x + threadIdx.x;     // grid covers N_GRAPHS*H = 524288
    if (i < N_NODES)      g_ideg[i] = 0;
    if (i < N_GRAPHS * H) g_gsum[i] = 0.f;
    if (i < N_GRAPHS)     g_gcnt[i] = 0.f;
}

__global__ void deg_kernel(const int* __restrict__ dst) {
    int e = blockIdx.x * blockDim.x + threadIdx.x;
    if (e < N_EDGES) atomicAdd(&g_ideg[dst[e]], 1);
}

__global__ void scan1_kernel() {
    __shared__ int sh[256];
    int tid = threadIdx.x;
    int base = blockIdx.x * 1024 + tid * 4;
    int v[4]; int s = 0;
#pragma unroll
    for (int k = 0; k < 4; ++k) {
        int i = base + k;
        v[k] = (i < N_NODES) ? g_ideg[i] : 0;
        s += v[k];
    }
    sh[tid] = s; __syncthreads();
#pragma unroll
    for (int o = 1; o < 256; o <<= 1) {
        int t = (tid >= o) ? sh[tid - o] : 0;
        __syncthreads(); sh[tid] += t; __syncthreads();
    }
    int run = sh[tid] - s;
#pragma unroll
    for (int k = 0; k < 4; ++k) {
        int i = base + k;
        if (i < N_NODES) g_off[i] = run;
        run += v[k];
    }
    if (tid == 255) g_bsum[blockIdx.x] = sh[255];
}

// scan finalize (block-sum prefix computed redundantly per block) + dinv + gcnt
__global__ void scan3_prep_kernel(const int* __restrict__ batch) {
    __shared__ int sh[256];
    int tid = threadIdx.x;
    int v = (tid < SCAN_NBLK) ? g_bsum[tid] : 0;
    sh[tid] = v; __syncthreads();
#pragma unroll
    for (int o = 1; o < 256; o <<= 1) {
        int t = (tid >= o) ? sh[tid - o] : 0;
        __syncthreads(); sh[tid] += t; __syncthreads();
    }
    sh[tid] -= v;                              // exclusive prefix
    __syncthreads();

    int i = blockIdx.x * 256 + tid;
    if (i < N_NODES) {
        g_off[i] += sh[i >> 10];
        g_dinv[i] = rsqrtf((float)g_ideg[i] + 1.0f);   // +1 self-loop
        atomicAdd(&g_gcnt[batch[i]], 1.0f);
    }
    if (i == 0) g_off[N_NODES] = N_EDGES;      // sentinel: cnt = off[i+1]-off[i]
}

// counting-sort fill; claims slots by counting g_ideg down (order irrelevant)
__global__ void fill_kernel(const int* __restrict__ src, const int* __restrict__ dst) {
    int e = blockIdx.x * blockDim.x + threadIdx.x;
    if (e < N_EDGES) {
        int d = dst[e];
        int pos = g_off[d] + atomicAdd(&g_ideg[d], -1) - 1;
        g_csr[pos] = src[e];
    }
}

// xs = dinv[node] * x (fp16); one float4 per thread. Runs AFTER scan3_prep.
__global__ void convert_x_kernel(const float* __restrict__ x) {
    int i = blockIdx.x * blockDim.x + threadIdx.x;     // N_NODES*128/4 threads exactly
    float dv = g_dinv[i >> 5];
    float4 v = ((const float4*)x)[i];
    ((__half2*)g_xs)[i * 2 + 0] = __floats2half2_rn(v.x * dv, v.y * dv);
    ((__half2*)g_xs)[i * 2 + 1] = __floats2half2_rn(v.z * dv, v.w * dv);
}

// transpose W[K,256] -> Wt [256,K] fp16
__global__ void split_w_kernel(const float* __restrict__ W,
                               __half* __restrict__ T, int K) {
    int i = blockIdx.x * blockDim.x + threadIdx.x;     // K*256 threads
    if (i < K * 256) {
        int k = i >> 8;
        int n = i & 255;
        T[n * K + k] = __float2half_rn(W[i]);          // coalesced read
    }
}

// ---------------- layer-1 aggregation on xs (128 fp16 cols, 256 B rows) -----
// One warp per node; half-warps process alternating edges, unroll 2.
__global__ void __launch_bounds__(256)
agg1_kernel()
{
    int warp = threadIdx.x >> 5;
    int lane = threadIdx.x & 31;
    int node = blockIdx.x * 8 + warp;          // grid.x = 12500, exact
    int half = lane >> 4;
    int coff = (lane & 15) * 8;                // 16 lanes x 8 halfs = 128 cols
    size_t rbase = (size_t)node * 128 + coff;

    __half2 acc[4];
#pragma unroll
    for (int q = 0; q < 4; ++q) acc[q] = __halves2half2(__ushort_as_half(0), __ushort_as_half(0));

    if (half == 0) {                            // self-loop term: xs[d]
        uint4 u = *(const uint4*)(g_xs + rbase);
        h2_acc(u, acc);
    }

    int beg = g_off[node];
    int cnt = g_off[node + 1] - beg;
    const int* nb = g_csr + beg;
    int j = half;
    for (; j + 2 < cnt; j += 4) {               // two edges per half-warp iter
        int s0 = nb[j], s1 = nb[j + 2];
        uint4 u0 = *(const uint4*)(g_xs + (size_t)s0 * 128 + coff);
        uint4 u1 = *(const uint4*)(g_xs + (size_t)s1 * 128 + coff);
        h2_acc(u0, acc);
        h2_acc(u1, acc);
    }
    if (j < cnt) {
        uint4 u = *(const uint4*)(g_xs + (size_t)nb[j] * 128 + coff);
        h2_acc(u, acc);
    }

    // combine half-warps on packed registers (lane i <-> i^16 share coff)
#pragma unroll
    for (int q = 0; q < 4; ++q) {
        uint32_t r = __shfl_xor_sync(0xffffffffu, *(uint32_t*)&acc[q], 16);
        acc[q] = __hadd2(acc[q], *(__half2*)&r);
    }

    if (half == 0) {
        float dv = g_dinv[node];
        __half2 h[4];
#pragma unroll
        for (int q = 0; q < 4; ++q) {
            float2 f = __half22float2(acc[q]);
            h[q] = __floats2half2_rn(f.x * dv, f.y * dv);
        }
        *(uint4*)(g_z1 + rbase) = *(uint4*)h;
    }
}

// ---------------- layer-2 aggregation on h1s (256 fp8 cols, 256 B rows) -----
// Half-warps process alternating edges; 16 lanes x uint4 (16 fp8) = full row.
__global__ void __launch_bounds__(256)
agg2_kernel()
{
    int warp = threadIdx.x >> 5;
    int lane = threadIdx.x & 31;
    int node = blockIdx.x * 8 + warp;          // grid.x = 12500
    int half = lane >> 4;
    int coff = (lane & 15) * 16;               // 16 lanes x 16 fp8 = 256 cols
    size_t rbase = (size_t)node * H + coff;

    __half2 acc[8];
#pragma unroll
    for (int q = 0; q < 8; ++q) acc[q] = __halves2half2(__ushort_as_half(0), __ushort_as_half(0));

    if (half == 0) {                            // self-loop term
        uint4 u = *(const uint4*)(g_h1s + rbase);
        f8_acc(u, acc);
    }

    int beg = g_off[node];
    int cnt = g_off[node + 1] - beg;
    const int* nb = g_csr + beg;
    int j = half;
    for (; j + 2 < cnt; j += 4) {               // two edges per half-warp iter
        int s0 = nb[j], s1 = nb[j + 2];
        uint4 u0 = *(const uint4*)(g_h1s + (size_t)s0 * H + coff);
        uint4 u1 = *(const uint4*)(g_h1s + (size_t)s1 * H + coff);
        f8_acc(u0, acc);
        f8_acc(u1, acc);
    }
    if (j < cnt) {
        uint4 u = *(const uint4*)(g_h1s + (size_t)nb[j] * H + coff);
        f8_acc(u, acc);
    }

    // combine half-warps
#pragma unroll
    for (int q = 0; q < 8; ++q) {
        uint32_t r = __shfl_xor_sync(0xffffffffu, *(uint32_t*)&acc[q], 16);
        acc[q] = __hadd2(acc[q], *(__half2*)&r);
    }

    if (half == 0) {
        float dv = g_dinv[node];
        __half2 h[8];
#pragma unroll
        for (int q = 0; q < 8; ++q) {
            float2 f = __half22float2(acc[q]);
            h[q] = __floats2half2_rn(f.x * dv, f.y * dv);
        }
        *(uint4*)(g_z2 + rbase)     = ((uint4*)h)[0];
        *(uint4*)(g_z2 + rbase + 8) = ((uint4*)h)[1];
    }
}

// ======== tensor-core GEMM (mma.sync fp16, single pass) =====================
// A: [M, K] fp16 row-major.  Wt: [256, K] fp16 row-major.
// mode 0: C(fp8) = fp8( dinv[row] * relu(A@Wt^T + bias) )
// mode 1: red.add relu(A@Wt^T + bias) into gsum[batch[row]]  (mean-pool)
#define ST_A  0
#define ST_B  16384
#define STAGE 32768
#define GEMM_SMEM (2 * STAGE)   // 65536

__global__ void __launch_bounds__(256, 2)
gemm_tc(const __half* __restrict__ Af, const __half* __restrict__ Bf,
        const float* __restrict__ bias, const float* __restrict__ dinv,
        unsigned char* __restrict__ C, const int* __restrict__ batch,
        float* __restrict__ gsum, int M, int K, int mode)
{
    extern __shared__ __align__(128) char smem[];
    const uint32_t sb = smem_u32(smem);
    const int tid = threadIdx.x;
    const int wid = tid >> 5;
    const int lane = tid & 31;
    const int tile0 = blockIdx.x * 128;      // M block
    const int nb = blockIdx.y * 128;         // N block

    const int kcn = K >> 6;

    const int lrow   = tid >> 3;                     // 0..31
    const int dstx   = ((tid & 7) << 4) ^ ((lrow & 7) << 4);   // swizzled 16B chunk
    const int colelm = (tid & 7) << 3;               // source col (elements)

    const int warp_m = wid & 1;
    const int warp_n = wid >> 1;
    const int arow  = warp_m * 64 + (lane & 15);
    const int axor  = (lane & 7) << 4;
    const int ac8   = (lane >> 4) << 4;
    const int brow  = warp_n * 32 + (lane & 7) + ((lane & 16) >> 1);
    const int bxor  = (lane & 7) << 4;
    const int bc8   = ((lane >> 3) & 1) << 4;

    float acc[4][4][4];
#pragma unroll
    for (int i = 0; i < 4; ++i)
#pragma unroll
        for (int j = 0; j < 4; ++j)
#pragma unroll
            for (int q = 0; q < 4; ++q) acc[i][j][q] = 0.f;

    auto load_stage = [&](int kc, int st) {
        const int kofs = (kc << 6) + colelm;
        uint32_t base = sb + st * STAGE;
#pragma unroll
        for (int j = 0; j < 4; ++j) {
            int row = lrow + (j << 5);
            int gr = tile0 + row; if (gr >= M) gr = M - 1;
            uint32_t rb = base + row * 128 + dstx;
            cp16(rb + ST_A, Af + (size_t)gr * K + kofs);
            cp16(rb + ST_B, Bf + (size_t)(nb + row) * K + kofs);
        }
    };

    load_stage(0, 0);
    CP_COMMIT();

    for (int ch = 0; ch < kcn; ++ch) {
        int st = ch & 1;
        if (ch + 1 < kcn) {
            load_stage(ch + 1, st ^ 1);
            CP_COMMIT();
            CP_WAIT1();
        } else {
            CP_WAIT0();
        }
        __syncthreads();

        uint32_t Abase = sb + st * STAGE + ST_A;
        uint32_t Bbase = sb + st * STAGE + ST_B;
#pragma unroll
        for (int k16 = 0; k16 < 4; ++k16) {
            uint32_t a[4][4], b[2][4];
            int cA = ((k16 << 5) + ac8) ^ axor;
            uint32_t aaddr = Abase + arow * 128 + cA;
#pragma unroll
            for (int tm = 0; tm < 4; ++tm) ldm_x4(a[tm], aaddr + tm * 2048);
            int cB = ((k16 << 5) + bc8) ^ bxor;
            uint32_t baddr = Bbase + brow * 128 + cB;
#pragma unroll
            for (int t2 = 0; t2 < 2; ++t2) ldm_x4(b[t2], baddr + t2 * 2048);
#pragma unroll
            for (int tm = 0; tm < 4; ++tm)
#pragma unroll
                for (int tn = 0; tn < 4; ++tn)
                    mma16816(acc[tm][tn], a[tm], &b[tn >> 1][(tn & 1) * 2]);
        }
        __syncthreads();
    }

    // ---- epilogue
    const int mrow0 = tile0 + warp_m * 64 + (lane >> 2);
    const int ncol0 = nb + warp_n * 32 + (lane & 3) * 2;
#pragma unroll
    for (int tm = 0; tm < 4; ++tm) {
        int r0 = mrow0 + tm * 16;
        int r1 = r0 + 8;
#pragma unroll
        for (int tn = 0; tn < 4; ++tn) {
            int c = ncol0 + tn * 8;
            const float2 bb = *(const float2*)(bias + c);
            float v0 = fmaxf(acc[tm][tn][0] + bb.x, 0.f);
            float v1 = fmaxf(acc[tm][tn][1] + bb.y, 0.f);
            float v2 = fmaxf(acc[tm][tn][2] + bb.x, 0.f);
            float v3 = fmaxf(acc[tm][tn][3] + bb.y, 0.f);
            if (mode == 0) {
                if (r0 < M) {
                    float dv0 = dinv[r0];
                    __nv_fp8x2_storage_t s = __nv_cvt_float2_to_fp8x2(
                        make_float2(v0 * dv0, v1 * dv0), __NV_SATFINITE, __NV_E4M3);
                    *(unsigned short*)(C + (size_t)r0 * H + c) = s;
                }
                if (r1 < M) {
                    float dv1 = dinv[r1];
                    __nv_fp8x2_storage_t s = __nv_cvt_float2_to_fp8x2(
                        make_float2(v2 * dv1, v3 * dv1), __NV_SATFINITE, __NV_E4M3);
                    *(unsigned short*)(C + (size_t)r1 * H + c) = s;
                }
            } else {
                if (r0 < M) {
                    float* p = gsum + (size_t)batch[r0] * H + c;
                    asm volatile("red.global.add.v2.f32 [%0], {%1, %2};"
                                 :: "l"(p), "f"(v0), "f"(v1) : "memory");
                }
                if (r1 < M) {
                    float* p = gsum + (size_t)batch[r1] * H + c;
                    asm volatile("red.global.add.v2.f32 [%0], {%1, %2};"
                                 :: "l"(p), "f"(v2), "f"(v3) : "memory");
                }
            }
        }
    }
}

// ---------------- classifier: mean, g@Wc+bc, log_softmax(64) ----------------
__global__ void classify_kernel(const float* __restrict__ gsum, const float* __restrict__ gcnt,
                                const float* __restrict__ Wc, const float* __restrict__ bc,
                                float* __restrict__ out)
{
    int gid = blockIdx.x;
    int j = threadIdx.x;                       // 64 threads
    __shared__ float sg[H];
    __shared__ float red2[2];

    float inv = 1.0f / fmaxf(gcnt[gid], 1.0f);
    for (int c = j; c < H; c += 64) sg[c] = gsum[(size_t)gid * H + c] * inv;
    __syncthreads();

    float acc = bc[j];
#pragma unroll
    for (int c = 0; c < H; ++c)
        acc = fmaf(sg[c], Wc[c * 64 + j], acc);

    float m = acc;
#pragma unroll
    for (int o = 16; o; o >>= 1) m = fmaxf(m, __shfl_xor_sync(0xffffffffu, m, o));
    if ((j & 31) == 0) red2[j >> 5] = m;
    __syncthreads();
    m = fmaxf(red2[0], red2[1]);
    __syncthreads();

    float e = expf(acc - m);
    float s = e;
#pragma unroll
    for (int o = 16; o; o >>= 1) s += __shfl_xor_sync(0xffffffffu, s, o);
    if ((j & 31) == 0) red2[j >> 5] = s;
    __syncthreads();
    s = red2[0] + red2[1];

    out[(size_t)gid * 64 + j] = acc - m - logf(s);
}

// ---------------- launch ----------------
extern "C" void kernel_launch(void* const* d_in, const int* in_sizes, int n_in,
                              void* d_out, int out_size)
{
    const float* x     = (const float*)d_in[0];
    const int*   eidx  = (const int*)d_in[1];     // int32 (JAX canonicalized)
    const int*   batch = (const int*)d_in[2];
    const float* W1    = (const float*)d_in[3];
    const float* b1    = (const float*)d_in[4];
    const float* W2    = (const float*)d_in[5];
    const float* b2    = (const float*)d_in[6];
    const float* Wc    = (const float*)d_in[7];
    const float* bc    = (const float*)d_in[8];
    float*       out   = (float*)d_out;

    const int* src = eidx;
    const int* dst = eidx + N_EDGES;

    float *dinv, *gsum, *gcnt;
    __half *z1, *z2, *w1, *w2;
    unsigned char* h1s;
    cudaGetSymbolAddress((void**)&dinv, g_dinv);
    cudaGetSymbolAddress((void**)&gsum, g_gsum);
    cudaGetSymbolAddress((void**)&gcnt, g_gcnt);
    cudaGetSymbolAddress((void**)&z1,  g_z1);
    cudaGetSymbolAddress((void**)&h1s, g_h1s);
    cudaGetSymbolAddress((void**)&z2,  g_z2);
    cudaGetSymbolAddress((void**)&w1,  g_w1);
    cudaGetSymbolAddress((void**)&w2,  g_w2);

    cudaFuncSetAttribute(gemm_tc, cudaFuncAttributeMaxDynamicSharedMemorySize, GEMM_SMEM);

    // weight transposes first (no deps)
    split_w_kernel<<<(128 * 256 + 255) / 256, 256>>>(W1, w1, 128);
    split_w_kernel<<<(256 * 256 + 255) / 256, 256>>>(W2, w2, 256);

    // prep + CSR build
    zero_kernel<<<(N_GRAPHS * H) / 256, 256>>>();
    deg_kernel<<<(N_EDGES + 255) / 256, 256>>>(dst);
    scan1_kernel<<<SCAN_NBLK, 256>>>();
    scan3_prep_kernel<<<(N_NODES + 255) / 256, 256>>>(batch);
    fill_kernel<<<(N_EDGES + 255) / 256, 256>>>(src, dst);
    convert_x_kernel<<<(N_NODES * 128 / 4) / 256, 256>>>(x);

    const int ntiles = (N_NODES + 127) / 128;   // 782
    dim3 ggrid(ntiles, 2);                      // N blocks of 128
    const int agrid = N_NODES / 8;              // 12500

    // layer 1: aggregate xs first, then GEMM w/ relu+dinv+fp8 epilogue
    agg1_kernel<<<agrid, 256>>>();
    gemm_tc<<<ggrid, 256, GEMM_SMEM>>>(z1, w1, b1, dinv, h1s, nullptr, nullptr,
                                       N_NODES, 128, 0);

    // layer 2: aggregate fp8 h1s, then GEMM w/ relu + fused mean-pool epilogue
    agg2_kernel<<<agrid, 256>>>();
    gemm_tc<<<ggrid, 256, GEMM_SMEM>>>(z2, w2, b2, nullptr, nullptr, batch, gsum,
                                       N_NODES, 256, 1);

    // classifier + log_softmax
    classify_kernel<<<N_GRAPHS, 64>>>(gsum, gcnt, Wc, bc, out);
}

// round 17
// speedup vs baseline: 1.1813x; 1.0452x over previous
#include <cuda_runtime.h>
#include <cuda_fp16.h>
#include <math.h>
#include <stdint.h>

#define N_NODES  100000
#define N_EDGES  1600000
#define N_GRAPHS 2048
#define H        256

#define SCAN_NBLK ((N_NODES + 1023) / 1024)   // 98 blocks of 1024

// ---------------- scratch (device globals; no allocs allowed) ----------------
__device__ int   g_ideg[N_NODES];
__device__ int   g_off[N_NODES + 1];          // exclusive scan + sentinel
__device__ int   g_csr[N_EDGES];
__device__ int   g_bsum[SCAN_NBLK];
__device__ float g_dinv[N_NODES];
__device__ float g_gsum[N_GRAPHS * H];
__device__ float g_gcnt[N_GRAPHS];
// fp16 node features
__device__ __half g_xs[(size_t)N_NODES * 128];    // dinv * x          (gather src, L1)
__device__ __half g_z1[(size_t)N_NODES * 128];    // dinv*(sum xs)     (gemm1 A)
__device__ __half g_h1s[(size_t)N_NODES * H];     // dinv*relu(z1W1+b1) (gather src, L2)
__device__ __half g_z2[(size_t)N_NODES * H];      // dinv*(sum h1s)    (gemm2 A)
__device__ __half g_w1[256 * 128];
__device__ __half g_w2[256 * 256];

// ================= warp-MMA helpers (sm_80-class, compile for compute_103) ==
__device__ __forceinline__ uint32_t smem_u32(const void* p) {
    uint32_t a;
    asm("{ .reg .u64 t; cvta.to.shared.u64 t, %1; cvt.u32.u64 %0, t; }" : "=r"(a) : "l"(p));
    return a;
}
__device__ __forceinline__ void ldm_x4(uint32_t* r, uint32_t addr) {
    asm volatile("ldmatrix.sync.aligned.m8n8.x4.shared.b16 {%0,%1,%2,%3}, [%4];"
                 : "=r"(r[0]), "=r"(r[1]), "=r"(r[2]), "=r"(r[3]) : "r"(addr));
}
__device__ __forceinline__ void mma16816(float* d, const uint32_t* a, const uint32_t* b) {
    asm volatile("mma.sync.aligned.m16n8k16.row.col.f32.f16.f16.f32 "
                 "{%0,%1,%2,%3}, {%4,%5,%6,%7}, {%8,%9}, {%0,%1,%2,%3};"
                 : "+f"(d[0]), "+f"(d[1]), "+f"(d[2]), "+f"(d[3])
                 : "r"(a[0]), "r"(a[1]), "r"(a[2]), "r"(a[3]), "r"(b[0]), "r"(b[1]));
}
__device__ __forceinline__ void cp16(uint32_t dst, const void* src) {
    asm volatile("cp.async.ca.shared.global [%0], [%1], 16;" :: "r"(dst), "l"(src));
}
#define CP_COMMIT() asm volatile("cp.async.commit_group;" ::: "memory")
#define CP_WAIT1()  asm volatile("cp.async.wait_group 1;" ::: "memory")
#define CP_WAIT0()  asm volatile("cp.async.wait_group 0;" ::: "memory")

// packed fp16 accumulate: 4 HADD2 per uint4
__device__ __forceinline__ void h2_acc(uint4 u, __half2* acc) {
    const __half2* hp = (const __half2*)&u;
#pragma unroll
    for (int q = 0; q < 4; ++q) acc[q] = __hadd2(acc[q], hp[q]);
}

// ---------------- fusedA: zero || transpose W1 || transpose W2 ---------------
// blocks [0,2048): zero; [2048,2176): W1 (128 blocks); [2176,2432): W2 (256 blocks)
__global__ void fusedA_kernel(const float* __restrict__ W1, const float* __restrict__ W2) {
    int b = blockIdx.x;
    if (b < 2048) {
        int i = b * 256 + threadIdx.x;                 // covers N_GRAPHS*H = 524288
        if (i < N_NODES)      g_ideg[i] = 0;
        if (i < N_GRAPHS * H) g_gsum[i] = 0.f;
        if (i < N_GRAPHS)     g_gcnt[i] = 0.f;
    } else if (b < 2048 + 128) {
        int i = (b - 2048) * 256 + threadIdx.x;        // 128*256 = 32768 elems
        int k = i >> 8, n = i & 255;
        g_w1[n * 128 + k] = __float2half_rn(W1[i]);
    } else {
        int i = (b - 2176) * 256 + threadIdx.x;        // 256*256 = 65536 elems
        int k = i >> 8, n = i & 255;
        g_w2[n * 256 + k] = __float2half_rn(W2[i]);
    }
}

__global__ void deg_kernel(const int* __restrict__ dst) {
    int e = blockIdx.x * blockDim.x + threadIdx.x;
    if (e < N_EDGES) atomicAdd(&g_ideg[dst[e]], 1);
}

__global__ void scan1_kernel() {
    __shared__ int sh[256];
    int tid = threadIdx.x;
    int base = blockIdx.x * 1024 + tid * 4;
    int v[4]; int s = 0;
#pragma unroll
    for (int k = 0; k < 4; ++k) {
        int i = base + k;
        v[k] = (i < N_NODES) ? g_ideg[i] : 0;
        s += v[k];
    }
    sh[tid] = s; __syncthreads();
#pragma unroll
    for (int o = 1; o < 256; o <<= 1) {
        int t = (tid >= o) ? sh[tid - o] : 0;
        __syncthreads(); sh[tid] += t; __syncthreads();
    }
    int run = sh[tid] - s;
#pragma unroll
    for (int k = 0; k < 4; ++k) {
        int i = base + k;
        if (i < N_NODES) g_off[i] = run;
        run += v[k];
    }
    if (tid == 255) g_bsum[blockIdx.x] = sh[255];
}

// scan finalize (block-sum prefix computed redundantly per block) + dinv + gcnt
__global__ void scan3_prep_kernel(const int* __restrict__ batch) {
    __shared__ int sh[256];
    int tid = threadIdx.x;
    int v = (tid < SCAN_NBLK) ? g_bsum[tid] : 0;
    sh[tid] = v; __syncthreads();
#pragma unroll
    for (int o = 1; o < 256; o <<= 1) {
        int t = (tid >= o) ? sh[tid - o] : 0;
        __syncthreads(); sh[tid] += t; __syncthreads();
    }
    sh[tid] -= v;                              // exclusive prefix
    __syncthreads();

    int i = blockIdx.x * 256 + tid;
    if (i < N_NODES) {
        g_off[i] += sh[i >> 10];
        g_dinv[i] = rsqrtf((float)g_ideg[i] + 1.0f);   // +1 self-loop
        atomicAdd(&g_gcnt[batch[i]], 1.0f);
    }
    if (i == 0) g_off[N_NODES] = N_EDGES;      // sentinel: cnt = off[i+1]-off[i]
}

// ---------------- fusedB: fill || convert_x (both depend only on scan3_prep)
// blocks [0,6250): counting-sort fill; [6250,18750): xs = dinv*x (fp16)
__global__ void fusedB_kernel(const int* __restrict__ src, const int* __restrict__ dst,
                              const float* __restrict__ x) {
    int b = blockIdx.x;
    if (b < 6250) {
        int e = b * 256 + threadIdx.x;
        if (e < N_EDGES) {
            int d = dst[e];
            int pos = g_off[d] + atomicAdd(&g_ideg[d], -1) - 1;
            g_csr[pos] = src[e];
        }
    } else {
        int i = (b - 6250) * 256 + threadIdx.x;        // N_NODES*128/4 = 3.2M exactly
        float dv = g_dinv[i >> 5];
        float4 v = ((const float4*)x)[i];
        ((__half2*)g_xs)[i * 2 + 0] = __floats2half2_rn(v.x * dv, v.y * dv);
        ((__half2*)g_xs)[i * 2 + 1] = __floats2half2_rn(v.z * dv, v.w * dv);
    }
}

// ---------------- layer-1 aggregation on xs (128 fp16 cols, 256 B rows) -----
// 4 warps/block (finer straggler granularity); half-warps alternate edges.
__global__ void __launch_bounds__(128)
agg1_kernel()
{
    int warp = threadIdx.x >> 5;
    int lane = threadIdx.x & 31;
    int node = blockIdx.x * 4 + warp;          // grid.x = 25000, exact
    int half = lane >> 4;
    int coff = (lane & 15) * 8;                // 16 lanes x 8 halfs = 128 cols
    size_t rbase = (size_t)node * 128 + coff;

    __half2 acc[4];
#pragma unroll
    for (int q = 0; q < 4; ++q) acc[q] = __halves2half2(__ushort_as_half(0), __ushort_as_half(0));

    if (half == 0) {                            // self-loop term: xs[d]
        uint4 u = *(const uint4*)(g_xs + rbase);
        h2_acc(u, acc);
    }

    int beg = g_off[node];
    int cnt = g_off[node + 1] - beg;
    const int* nb = g_csr + beg;
    int j = half;
    for (; j + 2 < cnt; j += 4) {               // two edges per half-warp iter
        int s0 = nb[j], s1 = nb[j + 2];
        uint4 u0 = *(const uint4*)(g_xs + (size_t)s0 * 128 + coff);
        uint4 u1 = *(const uint4*)(g_xs + (size_t)s1 * 128 + coff);
        h2_acc(u0, acc);
        h2_acc(u1, acc);
    }
    if (j < cnt) {
        uint4 u = *(const uint4*)(g_xs + (size_t)nb[j] * 128 + coff);
        h2_acc(u, acc);
    }

    // combine half-warps on packed registers (lane i <-> i^16 share coff)
#pragma unroll
    for (int q = 0; q < 4; ++q) {
        uint32_t r = __shfl_xor_sync(0xffffffffu, *(uint32_t*)&acc[q], 16);
        acc[q] = __hadd2(acc[q], *(__half2*)&r);
    }

    if (half == 0) {
        float dv = g_dinv[node];
        __half2 h[4];
#pragma unroll
        for (int q = 0; q < 4; ++q) {
            float2 f = __half22float2(acc[q]);
            h[q] = __floats2half2_rn(f.x * dv, f.y * dv);
        }
        *(uint4*)(g_z1 + rbase) = *(uint4*)h;
    }
}

// ---------------- layer-2 aggregation on h1s (256 fp16 cols, 512 B rows) ----
// 4 warps/block; full warp covers row, unroll-4, packed half2 accumulation.
__global__ void __launch_bounds__(128)
agg2_kernel()
{
    int warp = threadIdx.x >> 5;
    int lane = threadIdx.x & 31;
    int node = blockIdx.x * 4 + warp;          // grid.x = 25000
    int coff = lane * 8;
    size_t rbase = (size_t)node * H + coff;

    __half2 acc[4];
    {
        uint4 u = *(const uint4*)(g_h1s + rbase);   // self-loop term
        const __half2* hp = (const __half2*)&u;
#pragma unroll
        for (int q = 0; q < 4; ++q) acc[q] = hp[q];
    }

    int beg = g_off[node];
    int cnt = g_off[node + 1] - beg;
    const int* nb = g_csr + beg;
    int j = 0;
    for (; j + 3 < cnt; j += 4) {
        int s0 = nb[j], s1 = nb[j + 1], s2 = nb[j + 2], s3 = nb[j + 3];
        uint4 u0 = *(const uint4*)(g_h1s + (size_t)s0 * H + coff);
        uint4 u1 = *(const uint4*)(g_h1s + (size_t)s1 * H + coff);
        uint4 u2 = *(const uint4*)(g_h1s + (size_t)s2 * H + coff);
        uint4 u3 = *(const uint4*)(g_h1s + (size_t)s3 * H + coff);
        h2_acc(u0, acc);
        h2_acc(u1, acc);
        h2_acc(u2, acc);
        h2_acc(u3, acc);
    }
    for (; j < cnt; ++j) {
        uint4 u = *(const uint4*)(g_h1s + (size_t)nb[j] * H + coff);
        h2_acc(u, acc);
    }

    float dv = g_dinv[node];
    __half2 h[4];
#pragma unroll
    for (int q = 0; q < 4; ++q) {
        float2 f = __half22float2(acc[q]);
        h[q] = __floats2half2_rn(f.x * dv, f.y * dv);
    }
    *(uint4*)(g_z2 + rbase) = *(uint4*)h;
}

// ======== tensor-core GEMM (mma.sync fp16, single pass) =====================
// A: [M, K] fp16 row-major.  Wt: [256, K] fp16 row-major.
// mode 0: C = dinv[row] * relu(A@Wt^T + bias)  -> fp16 C
// mode 1: red.add relu(A@Wt^T + bias) into gsum[batch[row]]  (mean-pool)
#define ST_A  0
#define ST_B  16384
#define STAGE 32768
#define GEMM_SMEM (2 * STAGE)   // 65536

__global__ void __launch_bounds__(256, 2)
gemm_tc(const __half* __restrict__ Af, const __half* __restrict__ Bf,
        const float* __restrict__ bias, const float* __restrict__ dinv,
        __half* __restrict__ C, const int* __restrict__ batch,
        float* __restrict__ gsum, int M, int K, int mode)
{
    extern __shared__ __align__(128) char smem[];
    const uint32_t sb = smem_u32(smem);
    const int tid = threadIdx.x;
    const int wid = tid >> 5;
    const int lane = tid & 31;
    const int tile0 = blockIdx.x * 128;      // M block
    const int nb = blockIdx.y * 128;         // N block

    const int kcn = K >> 6;

    const int lrow   = tid >> 3;                     // 0..31
    const int dstx   = ((tid & 7) << 4) ^ ((lrow & 7) << 4);   // swizzled 16B chunk
    const int colelm = (tid & 7) << 3;               // source col (elements)

    const int warp_m = wid & 1;
    const int warp_n = wid >> 1;
    const int arow  = warp_m * 64 + (lane & 15);
    const int axor  = (lane & 7) << 4;
    const int ac8   = (lane >> 4) << 4;
    const int brow  = warp_n * 32 + (lane & 7) + ((lane & 16) >> 1);
    const int bxor  = (lane & 7) << 4;
    const int bc8   = ((lane >> 3) & 1) << 4;

    float acc[4][4][4];
#pragma unroll
    for (int i = 0; i < 4; ++i)
#pragma unroll
        for (int j = 0; j < 4; ++j)
#pragma unroll
            for (int q = 0; q < 4; ++q) acc[i][j][q] = 0.f;

    auto load_stage = [&](int kc, int st) {
        const int kofs = (kc << 6) + colelm;
        uint32_t base = sb + st * STAGE;
#pragma unroll
        for (int j = 0; j < 4; ++j) {
            int row = lrow + (j << 5);
            int gr = tile0 + row; if (gr >= M) gr = M - 1;
            uint32_t rb = base + row * 128 + dstx;
            cp16(rb + ST_A, Af + (size_t)gr * K + kofs);
            cp16(rb + ST_B, Bf + (size_t)(nb + row) * K + kofs);
        }
    };

    load_stage(0, 0);
    CP_COMMIT();

    for (int ch = 0; ch < kcn; ++ch) {
        int st = ch & 1;
        if (ch + 1 < kcn) {
            load_stage(ch + 1, st ^ 1);
            CP_COMMIT();
            CP_WAIT1();
        } else {
            CP_WAIT0();
        }
        __syncthreads();

        uint32_t Abase = sb + st * STAGE + ST_A;
        uint32_t Bbase = sb + st * STAGE + ST_B;
#pragma unroll
        for (int k16 = 0; k16 < 4; ++k16) {
            uint32_t a[4][4], b[2][4];
            int cA = ((k16 << 5) + ac8) ^ axor;
            uint32_t aaddr = Abase + arow * 128 + cA;
#pragma unroll
            for (int tm = 0; tm < 4; ++tm) ldm_x4(a[tm], aaddr + tm * 2048);
            int cB = ((k16 << 5) + bc8) ^ bxor;
            uint32_t baddr = Bbase + brow * 128 + cB;
#pragma unroll
            for (int t2 = 0; t2 < 2; ++t2) ldm_x4(b[t2], baddr + t2 * 2048);
#pragma unroll
            for (int tm = 0; tm < 4; ++tm)
#pragma unroll
                for (int tn = 0; tn < 4; ++tn)
                    mma16816(acc[tm][tn], a[tm], &b[tn >> 1][(tn & 1) * 2]);
        }
        __syncthreads();
    }

    // ---- epilogue
    const int mrow0 = tile0 + warp_m * 64 + (lane >> 2);
    const int ncol0 = nb + warp_n * 32 + (lane & 3) * 2;
#pragma unroll
    for (int tm = 0; tm < 4; ++tm) {
        int r0 = mrow0 + tm * 16;
        int r1 = r0 + 8;
#pragma unroll
        for (int tn = 0; tn < 4; ++tn) {
            int c = ncol0 + tn * 8;
            const float2 bb = *(const float2*)(bias + c);
            float v0 = fmaxf(acc[tm][tn][0] + bb.x, 0.f);
            float v1 = fmaxf(acc[tm][tn][1] + bb.y, 0.f);
            float v2 = fmaxf(acc[tm][tn][2] + bb.x, 0.f);
            float v3 = fmaxf(acc[tm][tn][3] + bb.y, 0.f);
            if (mode == 0) {
                if (r0 < M) {
                    float dv0 = dinv[r0];
                    *(__half2*)(C + (size_t)r0 * H + c) =
                        __floats2half2_rn(v0 * dv0, v1 * dv0);
                }
                if (r1 < M) {
                    float dv1 = dinv[r1];
                    *(__half2*)(C + (size_t)r1 * H + c) =
                        __floats2half2_rn(v2 * dv1, v3 * dv1);
                }
            } else {
                if (r0 < M) {
                    float* p = gsum + (size_t)batch[r0] * H + c;
                    asm volatile("red.global.add.v2.f32 [%0], {%1, %2};"
                                 :: "l"(p), "f"(v0), "f"(v1) : "memory");
                }
                if (r1 < M) {
                    float* p = gsum + (size_t)batch[r1] * H + c;
                    asm volatile("red.global.add.v2.f32 [%0], {%1, %2};"
                                 :: "l"(p), "f"(v2), "f"(v3) : "memory");
                }
            }
        }
    }
}

// ---------------- classifier: mean, g@Wc+bc, log_softmax(64) ----------------
__global__ void classify_kernel(const float* __restrict__ gsum, const float* __restrict__ gcnt,
                                const float* __restrict__ Wc, const float* __restrict__ bc,
                                float* __restrict__ out)
{
    int gid = blockIdx.x;
    int j = threadIdx.x;                       // 64 threads
    __shared__ float sg[H];
    __shared__ float red2[2];

    float inv = 1.0f / fmaxf(gcnt[gid], 1.0f);
    for (int c = j; c < H; c += 64) sg[c] = gsum[(size_t)gid * H + c] * inv;
    __syncthreads();

    float acc = bc[j];
#pragma unroll
    for (int c = 0; c < H; ++c)
        acc = fmaf(sg[c], Wc[c * 64 + j], acc);

    float m = acc;
#pragma unroll
    for (int o = 16; o; o >>= 1) m = fmaxf(m, __shfl_xor_sync(0xffffffffu, m, o));
    if ((j & 31) == 0) red2[j >> 5] = m;
    __syncthreads();
    m = fmaxf(red2[0], red2[1]);
    __syncthreads();

    float e = expf(acc - m);
    float s = e;
#pragma unroll
    for (int o = 16; o; o >>= 1) s += __shfl_xor_sync(0xffffffffu, s, o);
    if ((j & 31) == 0) red2[j >> 5] = s;
    __syncthreads();
    s = red2[0] + red2[1];

    out[(size_t)gid * 64 + j] = acc - m - logf(s);
}

// ---------------- launch ----------------
extern "C" void kernel_launch(void* const* d_in, const int* in_sizes, int n_in,
                              void* d_out, int out_size)
{
    const float* x     = (const float*)d_in[0];
    const int*   eidx  = (const int*)d_in[1];     // int32 (JAX canonicalized)
    const int*   batch = (const int*)d_in[2];
    const float* W1    = (const float*)d_in[3];
    const float* b1    = (const float*)d_in[4];
    const float* W2    = (const float*)d_in[5];
    const float* b2    = (const float*)d_in[6];
    const float* Wc    = (const float*)d_in[7];
    const float* bc    = (const float*)d_in[8];
    float*       out   = (float*)d_out;

    const int* src = eidx;
    const int* dst = eidx + N_EDGES;

    float *dinv, *gsum, *gcnt;
    __half *z1, *h1s, *z2, *w1, *w2;
    cudaGetSymbolAddress((void**)&dinv, g_dinv);
    cudaGetSymbolAddress((void**)&gsum, g_gsum);
    cudaGetSymbolAddress((void**)&gcnt, g_gcnt);
    cudaGetSymbolAddress((void**)&z1,  g_z1);
    cudaGetSymbolAddress((void**)&h1s, g_h1s);
    cudaGetSymbolAddress((void**)&z2,  g_z2);
    cudaGetSymbolAddress((void**)&w1,  g_w1);
    cudaGetSymbolAddress((void**)&w2,  g_w2);

    cudaFuncSetAttribute(gemm_tc, cudaFuncAttributeMaxDynamicSharedMemorySize, GEMM_SMEM);

    // fusedA: zero || W1-transpose || W2-transpose (all independent)
    fusedA_kernel<<<2432, 256>>>(W1, W2);
    deg_kernel<<<(N_EDGES + 255) / 256, 256>>>(dst);
    scan1_kernel<<<SCAN_NBLK, 256>>>();
    scan3_prep_kernel<<<(N_NODES + 255) / 256, 256>>>(batch);
    // fusedB: fill || convert_x (both depend only on scan3_prep)
    fusedB_kernel<<<18750, 256>>>(src, dst, x);

    const int ntiles = (N_NODES + 127) / 128;   // 782
    dim3 ggrid(ntiles, 2);                      // N blocks of 128
    const int agrid = N_NODES / 4;              // 25000 (4 warps/block)

    // layer 1: aggregate xs first, then GEMM w/ relu+dinv epilogue
    agg1_kernel<<<agrid, 128>>>();
    gemm_tc<<<ggrid, 256, GEMM_SMEM>>>(z1, w1, b1, dinv, h1s, nullptr, nullptr,
                                       N_NODES, 128, 0);

    // layer 2: aggregate h1s, then GEMM w/ relu + fused mean-pool epilogue
    agg2_kernel<<<agrid, 128>>>();
    gemm_tc<<<ggrid, 256, GEMM_SMEM>>>(z2, w2, b2, nullptr, nullptr, batch, gsum,
                                       N_NODES, 256, 1);

    // classifier + log_softmax
    classify_kernel<<<N_GRAPHS, 64>>>(gsum, gcnt, Wc, bc, out);
}